// round 2
// baseline (speedup 1.0000x reference)
#include <cuda_runtime.h>
#include <cstdint>

#define NPTS   34100
#define BATCHN 8
#define NGT    200
#define NLVL   5
#define NCAND  3500
#define MAXDET 300
#define IMGF   1280.0f
#define BIGF   2147483648.0f   // float32(2^31 - 1)

// output layout (float32, tuple flattened in return order)
#define OFF_MATCH  0
#define OFF_BOXES  272800
#define OFF_SCORES 282400
#define OFF_LABELS 284800
#define OFF_VALID  287200

__constant__ int c_loff[NLVL]  = {0, 25600, 32000, 33600, 34000};
__constant__ int c_lsize[NLVL] = {25600, 6400, 1600, 400, 100};
__constant__ int c_k[NLVL]     = {1000, 1000, 1000, 400, 100};
__constant__ int c_cbase[NLVL] = {0, 1000, 2000, 3000, 3400};

// scratch (static device globals; no allocation)
__device__ unsigned long long g_keys[BATCHN * NPTS];
__device__ float  g_cscore[BATCHN * NCAND];
__device__ float4 g_cbox[BATCHN * NCAND];
__device__ int    g_cgidx[BATCHN * NCAND];

// ---------------------------------------------------------------------------
// Stage 1: point -> gt box matching (argmin of area among containing boxes)
// ---------------------------------------------------------------------------
__global__ void match_kernel(const float* __restrict__ points,
                             const float* __restrict__ gt,
                             float* __restrict__ out) {
    const int b = blockIdx.y;
    __shared__ float sx1[NGT], sy1[NGT], sx2[NGT], sy2[NGT], sar[NGT];
    for (int j = threadIdx.x; j < NGT; j += blockDim.x) {
        const float* g = gt + (size_t)(b * NGT + j) * 4;
        float x1 = g[0], y1 = g[1], x2 = g[2], y2 = g[3];
        sx1[j] = x1; sy1[j] = y1; sx2[j] = x2; sy2[j] = y2;
        sar[j] = (x2 - x1) * (y2 - y1);
    }
    __syncthreads();
    int p = blockIdx.x * blockDim.x + threadIdx.x;
    if (p >= NPTS) return;
    float px = points[2 * p], py = points[2 * p + 1];
    float best = 3.4e38f;
    int bi = 0;
    bool any = false;
    #pragma unroll 4
    for (int j = 0; j < NGT; ++j) {
        bool in = (px >= sx1[j]) && (px <= sx2[j]) && (py >= sy1[j]) && (py <= sy2[j]);
        any = any || in;
        float c = in ? sar[j] : BIGF;
        if (c < best) { best = c; bi = j; }   // strict <  == first-min (jnp.argmin)
    }
    out[OFF_MATCH + (size_t)b * NPTS + p] = (float)(any ? bi : -1);
}

// ---------------------------------------------------------------------------
// Stage 2: exact per-(batch,level) top-k via 64-bit radix select on unique
// keys (ordered_score<<32 | ~local_idx), then compaction + box decode/clip.
// ---------------------------------------------------------------------------
__global__ void topk_kernel(const float* __restrict__ cls,
                            const float* __restrict__ reg,
                            const float* __restrict__ points) {
    const int bl = blockIdx.x;
    const int b = bl / NLVL, lvl = bl % NLVL;
    const int loff = c_loff[lvl], n = c_lsize[lvl], k = c_k[lvl];
    unsigned long long* keys = g_keys + (size_t)b * NPTS + loff;
    const float* logit = cls + (size_t)b * NPTS + loff;

    // phase 1: build keys
    for (int i = threadIdx.x; i < n; i += blockDim.x) {
        float s = 1.0f / (1.0f + expf(-logit[i]));   // sigmoid
        unsigned int u = __float_as_uint(s);
        u = (u & 0x80000000u) ? ~u : (u | 0x80000000u);  // order-preserving
        keys[i] = ((unsigned long long)u << 32) |
                  (unsigned long long)(0xFFFFFFFFu - (unsigned)i);
    }
    __syncthreads();

    // phase 2: radix select the exact k-th largest key (keys are unique)
    __shared__ unsigned int hist[256];
    __shared__ unsigned long long s_pref;
    __shared__ int s_remk;
    unsigned long long prefix = 0ULL;
    int remk = k;
    for (int pass = 0; pass < 8; ++pass) {
        const int shift = 56 - 8 * pass;
        const unsigned long long pmask =
            pass ? (~0ULL << (unsigned)(shift + 8)) : 0ULL;
        if (threadIdx.x < 256) hist[threadIdx.x] = 0u;
        __syncthreads();
        for (int i = threadIdx.x; i < n; i += blockDim.x) {
            unsigned long long kk = keys[i];
            if ((kk & pmask) == prefix)
                atomicAdd(&hist[(unsigned)(kk >> shift) & 0xFFu], 1u);
        }
        __syncthreads();
        if (threadIdx.x == 0) {
            int r = remk;
            int bin = 255;
            for (; bin > 0; --bin) {
                int h = (int)hist[bin];
                if (r <= h) break;
                r -= h;
            }
            s_pref = prefix | ((unsigned long long)bin << shift);
            s_remk = r;
        }
        __syncthreads();
        prefix = s_pref;
        remk = s_remk;
        __syncthreads();
    }
    // threshold = prefix; exactly k keys satisfy key >= prefix

    // phase 3: compaction (order irrelevant; NMS tie-breaks on global index)
    __shared__ int s_cnt;
    if (threadIdx.x == 0) s_cnt = 0;
    __syncthreads();
    const int cbase = b * NCAND + c_cbase[lvl];
    for (int i = threadIdx.x; i < n; i += blockDim.x) {
        unsigned long long kk = keys[i];
        if (kk >= prefix) {
            int slot = atomicAdd(&s_cnt, 1);
            int gidx = loff + i;
            unsigned int u = (unsigned int)(kk >> 32);
            unsigned int fb = (u & 0x80000000u) ? (u ^ 0x80000000u) : ~u;
            float score = __uint_as_float(fb);
            const float* rg = reg + ((size_t)b * NPTS + gidx) * 4;
            float px = points[2 * gidx], py = points[2 * gidx + 1];
            float l = rg[0] * IMGF, t = rg[1] * IMGF;
            float r = rg[2] * IMGF, bt = rg[3] * IMGF;
            float x1 = fminf(fmaxf(px - l, 0.0f), IMGF);
            float y1 = fminf(fmaxf(py - t, 0.0f), IMGF);
            float x2 = fminf(fmaxf(px + r, 0.0f), IMGF);
            float y2 = fminf(fmaxf(py + bt, 0.0f), IMGF);
            int ci = cbase + slot;
            g_cscore[ci] = score;
            g_cbox[ci] = make_float4(x1, y1, x2, y2);
            g_cgidx[ci] = gidx;
        }
    }
}

// ---------------------------------------------------------------------------
// Stage 3: sequential NMS, one block per batch image. Candidates are
// register-resident; argmax key = (ordered_score<<32 | ~global_idx) so ties
// resolve to lowest global index, matching the reference's candidate order.
// ---------------------------------------------------------------------------
__global__ void __launch_bounds__(1024, 1)
nms_kernel(float* __restrict__ out) {
    const int b = blockIdx.x;
    const int tid = threadIdx.x;
    const int lane = tid & 31, wid = tid >> 5;

    float cx1[4], cy1[4], cx2[4], cy2[4], car[4], csc[4];
    unsigned long long ckey[4];
    #pragma unroll
    for (int c = 0; c < 4; ++c) {
        int idx = tid + c * 1024;
        if (idx < NCAND) {
            int ci = b * NCAND + idx;
            float4 bx = g_cbox[ci];
            float sc = g_cscore[ci];
            int gi = g_cgidx[ci];
            cx1[c] = bx.x; cy1[c] = bx.y; cx2[c] = bx.z; cy2[c] = bx.w;
            car[c] = (bx.z - bx.x) * (bx.w - bx.y);
            csc[c] = sc;
            unsigned int u = __float_as_uint(sc);
            u = (u & 0x80000000u) ? ~u : (u | 0x80000000u);
            ckey[c] = (sc > 0.05f)
                    ? (((unsigned long long)u << 32) |
                       (unsigned long long)(~(unsigned)gi))
                    : 0ULL;
        } else {
            ckey[c] = 0ULL;
            cx1[c] = cy1[c] = cx2[c] = cy2[c] = car[c] = csc[c] = 0.0f;
        }
    }

    __shared__ unsigned long long s_warp[32];
    __shared__ unsigned long long s_max;
    __shared__ float s_pick[5];

    for (int it = 0; it < MAXDET; ++it) {
        // block argmax over 64-bit keys
        unsigned long long v = 0ULL;
        #pragma unroll
        for (int c = 0; c < 4; ++c) if (ckey[c] > v) v = ckey[c];
        #pragma unroll
        for (int o = 16; o; o >>= 1) {
            unsigned long long w = __shfl_down_sync(0xFFFFFFFFu, v, o);
            if (w > v) v = w;
        }
        if (lane == 0) s_warp[wid] = v;
        __syncthreads();
        if (wid == 0) {
            v = s_warp[lane];
            #pragma unroll
            for (int o = 16; o; o >>= 1) {
                unsigned long long w = __shfl_down_sync(0xFFFFFFFFu, v, o);
                if (w > v) v = w;
            }
            if (lane == 0) s_max = v;
        }
        __syncthreads();
        unsigned long long mk = s_max;
        const int oslot = b * MAXDET + it;

        if (mk == 0ULL) {
            if (tid == 0) {
                out[OFF_BOXES + (size_t)oslot * 4 + 0] = 0.0f;
                out[OFF_BOXES + (size_t)oslot * 4 + 1] = 0.0f;
                out[OFF_BOXES + (size_t)oslot * 4 + 2] = 0.0f;
                out[OFF_BOXES + (size_t)oslot * 4 + 3] = 0.0f;
                out[OFF_SCORES + oslot] = 0.0f;
                out[OFF_LABELS + oslot] = -1.0f;
                out[OFF_VALID + oslot] = 0.0f;
            }
            continue;  // uniform branch; all subsequent iterations also dead
        }

        // owner writes output + broadcast picked box
        #pragma unroll
        for (int c = 0; c < 4; ++c) {
            if (ckey[c] == mk) {
                out[OFF_BOXES + (size_t)oslot * 4 + 0] = cx1[c];
                out[OFF_BOXES + (size_t)oslot * 4 + 1] = cy1[c];
                out[OFF_BOXES + (size_t)oslot * 4 + 2] = cx2[c];
                out[OFF_BOXES + (size_t)oslot * 4 + 3] = cy2[c];
                out[OFF_SCORES + oslot] = csc[c];
                out[OFF_LABELS + oslot] = 0.0f;
                out[OFF_VALID + oslot] = 1.0f;
                s_pick[0] = cx1[c]; s_pick[1] = cy1[c];
                s_pick[2] = cx2[c]; s_pick[3] = cy2[c];
                s_pick[4] = car[c];
                ckey[c] = 0ULL;
            }
        }
        __syncthreads();
        float p1 = s_pick[0], p2 = s_pick[1], p3 = s_pick[2], p4 = s_pick[3];
        float pa = s_pick[4];
        #pragma unroll
        for (int c = 0; c < 4; ++c) {
            if (ckey[c] != 0ULL) {
                float xx1 = fmaxf(p1, cx1[c]);
                float yy1 = fmaxf(p2, cy1[c]);
                float xx2 = fminf(p3, cx2[c]);
                float yy2 = fminf(p4, cy2[c]);
                float inter = fmaxf(xx2 - xx1, 0.0f) * fmaxf(yy2 - yy1, 0.0f);
                float iou = inter / (pa + car[c] - inter + 1e-9f);
                if (iou > 0.5f) ckey[c] = 0ULL;
            }
        }
        // no sync needed: next iteration's reduce syncs order s_pick reuse
    }
}

extern "C" void kernel_launch(void* const* d_in, const int* in_sizes, int n_in,
                              void* d_out, int out_size) {
    const float* points = (const float*)d_in[0];   // (34100, 2)
    const float* gt     = (const float*)d_in[1];   // (8, 200, 4)
    const float* cls    = (const float*)d_in[2];   // (8, 34100, 1)
    const float* reg    = (const float*)d_in[3];   // (8, 34100, 4)
    float* out = (float*)d_out;

    dim3 mg((NPTS + 255) / 256, BATCHN);
    match_kernel<<<mg, 256>>>(points, gt, out);
    topk_kernel<<<BATCHN * NLVL, 1024>>>(cls, reg, points);
    nms_kernel<<<BATCHN, 1024>>>(out);
}

// round 3
// speedup vs baseline: 1.1759x; 1.1759x over previous
#include <cuda_runtime.h>
#include <cstdint>

#define NPTS   34100
#define BATCHN 8
#define NGT    200
#define NLVL   5
#define NCAND  3500
#define MAXDET 300
#define IMGF   1280.0f
#define BIGF   2147483648.0f   // float32(2^31 - 1)

// output layout (float32, tuple flattened in return order)
#define OFF_MATCH  0
#define OFF_BOXES  272800
#define OFF_SCORES 282400
#define OFF_LABELS 284800
#define OFF_VALID  287200

__constant__ int c_loff[NLVL]  = {0, 25600, 32000, 33600, 34000};
__constant__ int c_lsize[NLVL] = {25600, 6400, 1600, 400, 100};
__constant__ int c_k[NLVL]     = {1000, 1000, 1000, 400, 100};
__constant__ int c_cbase[NLVL] = {0, 1000, 2000, 3000, 3400};

// scratch (static device globals; no allocation)
__device__ unsigned long long g_keys[BATCHN * NPTS];
__device__ float  g_cscore[BATCHN * NCAND];
__device__ float4 g_cbox[BATCHN * NCAND];

// ---------------------------------------------------------------------------
// Stage 1: point -> gt box matching (argmin of area among containing boxes)
// GT boxes packed as float4 + area in smem; 2 points per thread.
// ---------------------------------------------------------------------------
__global__ void match_kernel(const float* __restrict__ points,
                             const float* __restrict__ gt,
                             float* __restrict__ out) {
    const int b = blockIdx.y;
    __shared__ float4 sbox[NGT];
    __shared__ float  sar[NGT];
    for (int j = threadIdx.x; j < NGT; j += blockDim.x) {
        float4 g = ((const float4*)gt)[b * NGT + j];
        sbox[j] = g;
        sar[j] = (g.z - g.x) * (g.w - g.y);
    }
    __syncthreads();
    int p0 = (blockIdx.x * blockDim.x + threadIdx.x) * 2;
    if (p0 >= NPTS) return;
    float2 pt0 = ((const float2*)points)[p0];
    bool has1 = (p0 + 1) < NPTS;
    float2 pt1 = has1 ? ((const float2*)points)[p0 + 1] : pt0;

    float best0 = BIGF, best1 = BIGF;
    int bi0 = 0, bi1 = 0;
    #pragma unroll 2
    for (int j = 0; j < NGT; ++j) {
        float4 g = sbox[j];
        float ar = sar[j];
        bool in0 = (pt0.x >= g.x) && (pt0.x <= g.z) && (pt0.y >= g.y) && (pt0.y <= g.w);
        bool in1 = (pt1.x >= g.x) && (pt1.x <= g.z) && (pt1.y >= g.y) && (pt1.y <= g.w);
        float c0 = in0 ? ar : BIGF;
        float c1 = in1 ? ar : BIGF;
        if (c0 < best0) { best0 = c0; bi0 = j; }   // strict < == first-min
        if (c1 < best1) { best1 = c1; bi1 = j; }
    }
    float* o = out + OFF_MATCH + (size_t)b * NPTS;
    o[p0] = (float)(best0 < BIGF ? bi0 : -1);
    if (has1) o[p0 + 1] = (float)(best1 < BIGF ? bi1 : -1);
}

// ---------------------------------------------------------------------------
// Stage 2: exact per-(batch,level) top-k via 64-bit radix select on unique
// keys (ordered_score<<32 | ~local_idx). Warp-aggregated histogram atomics,
// warp-parallel bin selection, early exit when chosen bin fully included.
// STABLE compaction so slot order == global point-index order (NMS tie-break).
// ---------------------------------------------------------------------------
__global__ void __launch_bounds__(1024)
topk_kernel(const float* __restrict__ cls,
            const float* __restrict__ reg,
            const float* __restrict__ points) {
    const int bl = blockIdx.x;
    const int b = bl / NLVL, lvl = bl % NLVL;
    const int loff = c_loff[lvl], n = c_lsize[lvl], k = c_k[lvl];
    const int tid = threadIdx.x;
    const int lane = tid & 31, wid = tid >> 5;
    unsigned long long* keys = g_keys + (size_t)b * NPTS + loff;
    const float* logit = cls + (size_t)b * NPTS + loff;

    // phase 1: build keys
    for (int i = tid; i < n; i += 1024) {
        float s = 1.0f / (1.0f + expf(-logit[i]));   // sigmoid
        unsigned int u = __float_as_uint(s);
        u = (u & 0x80000000u) ? ~u : (u | 0x80000000u);  // order-preserving
        keys[i] = ((unsigned long long)u << 32) |
                  (unsigned long long)(0xFFFFFFFFu - (unsigned)i);
    }
    __syncthreads();

    // phase 2: radix select exact k-th largest key (unique keys)
    unsigned long long prefix = 0ULL;
    if (k < n) {
        __shared__ int hist[256];
        __shared__ unsigned long long s_pref;
        __shared__ int s_remk;
        __shared__ int s_done;
        int remk = k;
        const int iters = (n + 1023) >> 10;
        for (int pass = 0; pass < 8; ++pass) {
            const int shift = 56 - 8 * pass;
            const unsigned long long pmask =
                pass ? (~0ULL << (unsigned)(shift + 8)) : 0ULL;
            if (tid < 256) hist[tid] = 0;
            __syncthreads();
            for (int it = 0; it < iters; ++it) {
                int i = it * 1024 + tid;
                bool v = (i < n);
                unsigned long long kk = v ? keys[i] : 0ULL;
                int bin = (v && ((kk & pmask) == prefix))
                        ? (int)((kk >> shift) & 255) : 256;
                unsigned grp = __match_any_sync(0xFFFFFFFFu, bin);
                int leader = __ffs(grp) - 1;
                if (lane == leader && bin < 256)
                    atomicAdd(&hist[bin], __popc(grp));
            }
            __syncthreads();
            if (wid == 0) {
                // lane l owns bins [8l, 8l+7]
                int h[8];
                int t8 = 0;
                #pragma unroll
                for (int q = 0; q < 8; ++q) { h[q] = hist[lane * 8 + q]; t8 += h[q]; }
                // inclusive suffix sum over lanes (sum of lanes >= l)
                int psum = t8;
                #pragma unroll
                for (int o = 1; o < 32; o <<= 1) {
                    int w = __shfl_down_sync(0xFFFFFFFFu, psum, o);
                    if (lane + o < 32) psum += w;
                }
                int above = psum - t8;  // strictly higher lanes
                if (above < remk && remk <= above + t8) {
                    int r = remk - above;
                    int c = 0;
                    #pragma unroll
                    for (int q = 7; q >= 0; --q) {
                        if (r <= c + h[q]) {
                            s_pref = prefix | ((unsigned long long)(lane * 8 + q) << shift);
                            s_remk = r - c;
                            s_done = (r - c == h[q]) ? 1 : 0;
                            break;
                        }
                        c += h[q];
                    }
                }
            }
            __syncthreads();
            prefix = s_pref;
            remk = s_remk;
            if (s_done) break;   // all of chosen bin included -> threshold exact
            __syncthreads();
        }
    }
    // exactly k keys satisfy key >= prefix

    // phase 3: STABLE compaction (slot order == local index order)
    __shared__ int s_wexcl[32];
    __shared__ int s_total;
    __shared__ int s_base[2];
    if (tid == 0) s_base[0] = 0;
    __syncthreads();
    int par = 0;
    const int citers = (n + 1023) >> 10;
    const int cbase = b * NCAND + c_cbase[lvl];
    for (int it = 0; it < citers; ++it) {
        int i = it * 1024 + tid;
        unsigned long long kk = (i < n) ? keys[i] : 0ULL;
        bool pred = (i < n) && (kk >= prefix);
        unsigned ball = __ballot_sync(0xFFFFFFFFu, pred);
        int rank = __popc(ball & ((1u << lane) - 1u));
        if (lane == 0) s_wexcl[wid] = __popc(ball);
        __syncthreads();
        if (wid == 0) {
            int v = s_wexcl[lane];
            int incl = v;
            #pragma unroll
            for (int o = 1; o < 32; o <<= 1) {
                int w = __shfl_up_sync(0xFFFFFFFFu, incl, o);
                if (lane >= o) incl += w;
            }
            s_wexcl[lane] = incl - v;
            if (lane == 31) s_total = incl;
        }
        __syncthreads();
        int base = s_base[par];
        if (pred) {
            int slot = base + s_wexcl[wid] + rank;
            int gidx = loff + i;
            unsigned int u = (unsigned int)(kk >> 32);
            unsigned int fb = (u & 0x80000000u) ? (u ^ 0x80000000u) : ~u;
            float score = __uint_as_float(fb);
            const float4 rg = ((const float4*)reg)[(size_t)b * NPTS + gidx];
            float2 p = ((const float2*)points)[gidx];
            float l = rg.x * IMGF, t = rg.y * IMGF;
            float r = rg.z * IMGF, bt = rg.w * IMGF;
            float x1 = fminf(fmaxf(p.x - l, 0.0f), IMGF);
            float y1 = fminf(fmaxf(p.y - t, 0.0f), IMGF);
            float x2 = fminf(fmaxf(p.x + r, 0.0f), IMGF);
            float y2 = fminf(fmaxf(p.y + bt, 0.0f), IMGF);
            int ci = cbase + slot;
            g_cscore[ci] = score;
            g_cbox[ci] = make_float4(x1, y1, x2, y2);
        }
        if (tid == 0) s_base[par ^ 1] = base + s_total;
        par ^= 1;
        __syncthreads();
    }
}

// ---------------------------------------------------------------------------
// 64-bit warp max via two HW redux ops (live lo bits are >= 0xFFFFF000, dead
// keys are all-zero, so masking non-max-hi lanes' lo to 0 is safe).
// ---------------------------------------------------------------------------
__device__ __forceinline__ unsigned long long warp_max_u64(unsigned long long v) {
    unsigned hi = (unsigned)(v >> 32), lo = (unsigned)v;
    unsigned mhi = __reduce_max_sync(0xFFFFFFFFu, hi);
    unsigned mlo = __reduce_max_sync(0xFFFFFFFFu, (hi == mhi) ? lo : 0u);
    return ((unsigned long long)mhi << 32) | mlo;
}

// ---------------------------------------------------------------------------
// Stage 3: sequential NMS, one block per image. Key = score<<32 | ~slot
// (stable slots => slot order == global index order == reference tie-break).
// Picked box fetched by ALL threads via broadcast LDG: only 2 barriers/iter.
// ---------------------------------------------------------------------------
__global__ void __launch_bounds__(1024, 1)
nms_kernel(float* __restrict__ out) {
    const int b = blockIdx.x;
    const int tid = threadIdx.x;
    const int lane = tid & 31, wid = tid >> 5;

    float cx1[4], cy1[4], cx2[4], cy2[4], car[4], csc[4];
    unsigned long long ckey[4];
    #pragma unroll
    for (int c = 0; c < 4; ++c) {
        int slot = tid + c * 1024;
        if (slot < NCAND) {
            int ci = b * NCAND + slot;
            float4 bx = g_cbox[ci];
            float sc = g_cscore[ci];
            cx1[c] = bx.x; cy1[c] = bx.y; cx2[c] = bx.z; cy2[c] = bx.w;
            car[c] = (bx.z - bx.x) * (bx.w - bx.y);
            csc[c] = sc;
            unsigned int u = __float_as_uint(sc);
            u = (u & 0x80000000u) ? ~u : (u | 0x80000000u);
            ckey[c] = (sc > 0.05f)
                    ? (((unsigned long long)u << 32) |
                       (unsigned long long)(~(unsigned)slot))
                    : 0ULL;
        } else {
            ckey[c] = 0ULL;
            cx1[c] = cy1[c] = cx2[c] = cy2[c] = car[c] = csc[c] = 0.0f;
        }
    }

    __shared__ unsigned long long s_warp[32];
    __shared__ unsigned long long s_max;

    for (int it = 0; it < MAXDET; ++it) {
        // block argmax over 64-bit keys
        unsigned long long v = ckey[0];
        if (ckey[1] > v) v = ckey[1];
        if (ckey[2] > v) v = ckey[2];
        if (ckey[3] > v) v = ckey[3];
        v = warp_max_u64(v);
        if (lane == 0) s_warp[wid] = v;
        __syncthreads();
        if (wid == 0) {
            unsigned long long w = warp_max_u64(s_warp[lane]);
            if (lane == 0) s_max = w;
        }
        __syncthreads();
        const unsigned long long mk = s_max;

        if (mk == 0ULL) {
            // no candidates left: fill remaining output slots, uniform exit
            for (int jt = it + tid; jt < MAXDET; jt += 1024) {
                int oslot = b * MAXDET + jt;
                out[OFF_BOXES + (size_t)oslot * 4 + 0] = 0.0f;
                out[OFF_BOXES + (size_t)oslot * 4 + 1] = 0.0f;
                out[OFF_BOXES + (size_t)oslot * 4 + 2] = 0.0f;
                out[OFF_BOXES + (size_t)oslot * 4 + 3] = 0.0f;
                out[OFF_SCORES + oslot] = 0.0f;
                out[OFF_LABELS + oslot] = -1.0f;
                out[OFF_VALID + oslot] = 0.0f;
            }
            return;
        }

        const int slot = (int)(~(unsigned)mk);       // picked candidate slot
        const int oslot = b * MAXDET + it;

        // owner writes output + clears its key (no ordering needed vs others)
        if ((slot & 1023) == tid) {
            int c = slot >> 10;
            out[OFF_BOXES + (size_t)oslot * 4 + 0] = cx1[c];
            out[OFF_BOXES + (size_t)oslot * 4 + 1] = cy1[c];
            out[OFF_BOXES + (size_t)oslot * 4 + 2] = cx2[c];
            out[OFF_BOXES + (size_t)oslot * 4 + 3] = cy2[c];
            out[OFF_SCORES + oslot] = csc[c];
            out[OFF_LABELS + oslot] = 0.0f;
            out[OFF_VALID + oslot] = 1.0f;
            ckey[c] = 0ULL;
        }

        // all threads fetch the picked box via broadcast load (L1-warm)
        float4 pb = __ldg(&g_cbox[b * NCAND + slot]);
        float pa = (pb.z - pb.x) * (pb.w - pb.y);

        #pragma unroll
        for (int c = 0; c < 4; ++c) {
            if (ckey[c] != 0ULL) {
                float xx1 = fmaxf(pb.x, cx1[c]);
                float yy1 = fmaxf(pb.y, cy1[c]);
                float xx2 = fminf(pb.z, cx2[c]);
                float yy2 = fminf(pb.w, cy2[c]);
                float inter = fmaxf(xx2 - xx1, 0.0f) * fmaxf(yy2 - yy1, 0.0f);
                float iou = inter / (pa + car[c] - inter + 1e-9f);
                if (iou > 0.5f) ckey[c] = 0ULL;
            }
        }
        // next iteration's barrier orders ckey/s_warp reuse
    }
}

extern "C" void kernel_launch(void* const* d_in, const int* in_sizes, int n_in,
                              void* d_out, int out_size) {
    const float* points = (const float*)d_in[0];   // (34100, 2)
    const float* gt     = (const float*)d_in[1];   // (8, 200, 4)
    const float* cls    = (const float*)d_in[2];   // (8, 34100, 1)
    const float* reg    = (const float*)d_in[3];   // (8, 34100, 4)
    float* out = (float*)d_out;

    dim3 mg((NPTS + 511) / 512, BATCHN);
    match_kernel<<<mg, 256>>>(points, gt, out);
    topk_kernel<<<BATCHN * NLVL, 1024>>>(cls, reg, points);
    nms_kernel<<<BATCHN, 1024>>>(out);
}

// round 4
// speedup vs baseline: 1.6307x; 1.3867x over previous
#include <cuda_runtime.h>
#include <cstdint>

#define NPTS   34100
#define BATCHN 8
#define NGT    200
#define NLVL   5
#define NCAND  3500
#define MAXDET 300
#define IMGF   1280.0f
#define BIGF   2147483648.0f   // float32(2^31 - 1)
#define NWORDS 112             // row stride in words (110 used, uint4 aligned)

// output layout (float32, tuple flattened in return order)
#define OFF_MATCH  0
#define OFF_BOXES  272800
#define OFF_SCORES 282400
#define OFF_LABELS 284800
#define OFF_VALID  287200

__constant__ int c_loff[NLVL]  = {0, 25600, 32000, 33600, 34000};
__constant__ int c_lsize[NLVL] = {25600, 6400, 1600, 400, 100};
__constant__ int c_k[NLVL]     = {1000, 1000, 1000, 400, 100};
__constant__ int c_cbase[NLVL] = {0, 1000, 2000, 3000, 3400};

// scratch (static device globals; no allocation)
__device__ unsigned long long g_keys[BATCHN * NPTS];
__device__ unsigned long long g_ckey[BATCHN * NCAND];
__device__ float  g_cscore[BATCHN * NCAND];
__device__ float4 g_cbox[BATCHN * NCAND];
// sorted-by-key-desc candidate arrays
__device__ float4 g_sbox[BATCHN * NCAND];
__device__ float  g_sscore[BATCHN * NCAND];
__device__ float  g_sarea[BATCHN * NCAND];
__device__ int    g_nvalid[BATCHN];
// suppression bit matrix: row i -> bits over j (sorted order)
__device__ unsigned g_mask[BATCHN * NCAND * NWORDS];

// ---------------------------------------------------------------------------
// Stage 1: point -> gt box matching (argmin of area among containing boxes)
// 4 points per thread; GT boxes as float4+area in smem.
// ---------------------------------------------------------------------------
__global__ void match_kernel(const float* __restrict__ points,
                             const float* __restrict__ gt,
                             float* __restrict__ out) {
    const int b = blockIdx.y;
    __shared__ float4 sbox[NGT];
    __shared__ float  sar[NGT];
    for (int j = threadIdx.x; j < NGT; j += blockDim.x) {
        float4 g = ((const float4*)gt)[b * NGT + j];
        sbox[j] = g;
        sar[j] = (g.z - g.x) * (g.w - g.y);
    }
    __syncthreads();
    int p0 = (blockIdx.x * blockDim.x + threadIdx.x) * 4;   // NPTS % 4 == 0
    if (p0 >= NPTS) return;
    float4 q0 = ((const float4*)points)[(p0 >> 1) + 0];
    float4 q1 = ((const float4*)points)[(p0 >> 1) + 1];
    float px[4] = {q0.x, q0.z, q1.x, q1.z};
    float py[4] = {q0.y, q0.w, q1.y, q1.w};
    float best[4] = {BIGF, BIGF, BIGF, BIGF};
    int bi[4] = {0, 0, 0, 0};
    #pragma unroll 2
    for (int j = 0; j < NGT; ++j) {
        float4 g = sbox[j];
        float ar = sar[j];
        #pragma unroll
        for (int t = 0; t < 4; ++t) {
            bool in = (px[t] >= g.x) && (px[t] <= g.z) &&
                      (py[t] >= g.y) && (py[t] <= g.w);
            float c = in ? ar : BIGF;
            if (c < best[t]) { best[t] = c; bi[t] = j; }  // strict < == first-min
        }
    }
    float* o = out + OFF_MATCH + (size_t)b * NPTS + p0;
    #pragma unroll
    for (int t = 0; t < 4; ++t)
        o[t] = (float)(best[t] < BIGF ? bi[t] : -1);
}

// ---------------------------------------------------------------------------
// Stage 2: exact per-(batch,level) top-k via 64-bit radix select on unique
// keys (ordered_score<<32 | ~local_idx); early-exit when bin fully included.
// Stable compaction: slot order == global index order (reference tie-break).
// ---------------------------------------------------------------------------
__global__ void __launch_bounds__(1024)
topk_kernel(const float* __restrict__ cls,
            const float* __restrict__ reg,
            const float* __restrict__ points) {
    const int bl = blockIdx.x;
    const int b = bl / NLVL, lvl = bl % NLVL;
    const int loff = c_loff[lvl], n = c_lsize[lvl], k = c_k[lvl];
    const int tid = threadIdx.x;
    const int lane = tid & 31, wid = tid >> 5;
    unsigned long long* keys = g_keys + (size_t)b * NPTS + loff;
    const float* logit = cls + (size_t)b * NPTS + loff;

    for (int i = tid; i < n; i += 1024) {
        float s = 1.0f / (1.0f + expf(-logit[i]));   // sigmoid
        unsigned int u = __float_as_uint(s);
        u = (u & 0x80000000u) ? ~u : (u | 0x80000000u);  // order-preserving
        keys[i] = ((unsigned long long)u << 32) |
                  (unsigned long long)(0xFFFFFFFFu - (unsigned)i);
    }
    __syncthreads();

    unsigned long long prefix = 0ULL;
    if (k < n) {
        __shared__ int hist[256];
        __shared__ unsigned long long s_pref;
        __shared__ int s_remk;
        __shared__ int s_done;
        int remk = k;
        const int iters = (n + 1023) >> 10;
        for (int pass = 0; pass < 8; ++pass) {
            const int shift = 56 - 8 * pass;
            const unsigned long long pmask =
                pass ? (~0ULL << (unsigned)(shift + 8)) : 0ULL;
            if (tid < 256) hist[tid] = 0;
            __syncthreads();
            for (int it = 0; it < iters; ++it) {
                int i = it * 1024 + tid;
                bool v = (i < n);
                unsigned long long kk = v ? keys[i] : 0ULL;
                int bin = (v && ((kk & pmask) == prefix))
                        ? (int)((kk >> shift) & 255) : 256;
                unsigned grp = __match_any_sync(0xFFFFFFFFu, bin);
                int leader = __ffs(grp) - 1;
                if (lane == leader && bin < 256)
                    atomicAdd(&hist[bin], __popc(grp));
            }
            __syncthreads();
            if (wid == 0) {
                int h[8];
                int t8 = 0;
                #pragma unroll
                for (int q = 0; q < 8; ++q) { h[q] = hist[lane * 8 + q]; t8 += h[q]; }
                int psum = t8;
                #pragma unroll
                for (int o = 1; o < 32; o <<= 1) {
                    int w = __shfl_down_sync(0xFFFFFFFFu, psum, o);
                    if (lane + o < 32) psum += w;
                }
                int above = psum - t8;
                if (above < remk && remk <= above + t8) {
                    int r = remk;
                    int c = above;
                    #pragma unroll
                    for (int q = 7; q >= 0; --q) {
                        if (r <= c + h[q]) {
                            s_pref = prefix | ((unsigned long long)(lane * 8 + q) << shift);
                            s_remk = r - c;
                            s_done = (r - c == h[q]) ? 1 : 0;
                            break;
                        }
                        c += h[q];
                    }
                }
            }
            __syncthreads();
            prefix = s_pref;
            remk = s_remk;
            if (s_done) break;
            __syncthreads();
        }
    }

    // stable compaction
    __shared__ int s_wexcl[32];
    __shared__ int s_total;
    __shared__ int s_base[2];
    if (tid == 0) s_base[0] = 0;
    __syncthreads();
    int par = 0;
    const int citers = (n + 1023) >> 10;
    const int cbase = b * NCAND + c_cbase[lvl];
    for (int it = 0; it < citers; ++it) {
        int i = it * 1024 + tid;
        unsigned long long kk = (i < n) ? keys[i] : 0ULL;
        bool pred = (i < n) && (kk >= prefix);
        unsigned ball = __ballot_sync(0xFFFFFFFFu, pred);
        int rank = __popc(ball & ((1u << lane) - 1u));
        if (lane == 0) s_wexcl[wid] = __popc(ball);
        __syncthreads();
        if (wid == 0) {
            int v = s_wexcl[lane];
            int incl = v;
            #pragma unroll
            for (int o = 1; o < 32; o <<= 1) {
                int w = __shfl_up_sync(0xFFFFFFFFu, incl, o);
                if (lane >= o) incl += w;
            }
            s_wexcl[lane] = incl - v;
            if (lane == 31) s_total = incl;
        }
        __syncthreads();
        int base = s_base[par];
        if (pred) {
            int slot = c_cbase[lvl] + base + s_wexcl[wid] + rank;  // image-local
            int gidx = loff + i;
            unsigned int u = (unsigned int)(kk >> 32);
            unsigned int fb = (u & 0x80000000u) ? (u ^ 0x80000000u) : ~u;
            float score = __uint_as_float(fb);
            const float4 rg = ((const float4*)reg)[(size_t)b * NPTS + gidx];
            float2 p = ((const float2*)points)[gidx];
            float l = rg.x * IMGF, t = rg.y * IMGF;
            float r = rg.z * IMGF, bt = rg.w * IMGF;
            float x1 = fminf(fmaxf(p.x - l, 0.0f), IMGF);
            float y1 = fminf(fmaxf(p.y - t, 0.0f), IMGF);
            float x2 = fminf(fmaxf(p.x + r, 0.0f), IMGF);
            float y2 = fminf(fmaxf(p.y + bt, 0.0f), IMGF);
            int ci = b * NCAND + slot;
            g_cscore[ci] = score;
            g_cbox[ci] = make_float4(x1, y1, x2, y2);
            // NMS pick-order key; 0 for below score threshold (never pickable)
            g_ckey[ci] = (score > 0.05f)
                       ? (((unsigned long long)u << 32) |
                          (unsigned long long)(0xFFFFFFFFu - (unsigned)slot))
                       : 0ULL;
        }
        if (tid == 0) s_base[par ^ 1] = base + s_total;
        par ^= 1;
        __syncthreads();
    }
}

// ---------------------------------------------------------------------------
// Stage 3a: per-image bitonic sort (desc) of candidate keys + gather.
// ---------------------------------------------------------------------------
__global__ void __launch_bounds__(1024)
sort_kernel() {
    const int b = blockIdx.x;
    const int tid = threadIdx.x;
    __shared__ unsigned long long sk[4096];
    for (int i = tid; i < 4096; i += 1024)
        sk[i] = (i < NCAND) ? g_ckey[b * NCAND + i] : 0ULL;
    __syncthreads();

    for (int k = 2; k <= 4096; k <<= 1) {
        for (int j = k >> 1; j > 0; j >>= 1) {
            for (int i = tid; i < 4096; i += 1024) {
                int ixj = i ^ j;
                if (ixj > i) {
                    bool up = ((i & k) == 0);   // ascending
                    unsigned long long a = sk[i], c = sk[ixj];
                    if ((a > c) == up) { sk[i] = c; sk[ixj] = a; }
                }
            }
            __syncthreads();
        }
    }

    // gather in descending order; count valid (key != 0)
    __shared__ int s_nv;
    if (tid == 0) s_nv = 0;
    __syncthreads();
    int cnt = 0;
    for (int p = tid; p < NCAND; p += 1024) {
        unsigned long long key = sk[4095 - p];
        if (key) {
            cnt++;
            int slot = (int)(0xFFFFFFFFu - (unsigned)key);
            float4 bx = g_cbox[b * NCAND + slot];
            g_sbox[b * NCAND + p] = bx;
            g_sscore[b * NCAND + p] = g_cscore[b * NCAND + slot];
            g_sarea[b * NCAND + p] = (bx.z - bx.x) * (bx.w - bx.y);
        } else {
            g_sbox[b * NCAND + p] = make_float4(0.f, 0.f, 0.f, 0.f);
            g_sscore[b * NCAND + p] = 0.f;
            g_sarea[b * NCAND + p] = 0.f;
        }
    }
    cnt += __shfl_down_sync(0xFFFFFFFFu, cnt, 16);
    cnt += __shfl_down_sync(0xFFFFFFFFu, cnt, 8);
    cnt += __shfl_down_sync(0xFFFFFFFFu, cnt, 4);
    cnt += __shfl_down_sync(0xFFFFFFFFu, cnt, 2);
    cnt += __shfl_down_sync(0xFFFFFFFFu, cnt, 1);
    if ((tid & 31) == 0) atomicAdd(&s_nv, cnt);
    __syncthreads();
    if (tid == 0) g_nvalid[b] = s_nv;
}

// ---------------------------------------------------------------------------
// Stage 3b: suppression bit matrix. One warp per sorted row i; ballot builds
// a 32-bit suppression word per iteration. Exact reference IoU semantics.
// ---------------------------------------------------------------------------
__global__ void __launch_bounds__(256)
mask_kernel() {
    const int b = blockIdx.y;
    const int lane = threadIdx.x & 31;
    const int i = blockIdx.x * 8 + (threadIdx.x >> 5);
    if (i >= NCAND) return;
    if (i >= g_nvalid[b]) return;       // rows never read by scan

    const float4 bi = g_sbox[b * NCAND + i];
    const float ai = g_sarea[b * NCAND + i];
    unsigned* row = g_mask + ((size_t)(b * NCAND) + i) * NWORDS;

    const int iw = i >> 5;
    for (int jw = lane; jw < iw; jw += 32) row[jw] = 0u;   // below diagonal
    for (int jw = iw; jw < NWORDS; ++jw) {
        int j = jw * 32 + lane;
        bool sup = false;
        if (j > i && j < NCAND) {
            float4 bj = g_sbox[b * NCAND + j];
            float x1 = fmaxf(bi.x, bj.x);
            float y1 = fmaxf(bi.y, bj.y);
            float x2 = fminf(bi.z, bj.z);
            float y2 = fminf(bi.w, bj.w);
            float inter = fmaxf(x2 - x1, 0.0f) * fmaxf(y2 - y1, 0.0f);
            float aj = g_sarea[b * NCAND + j];
            float iou = inter / (ai + aj - inter + 1e-9f);
            sup = iou > 0.5f;
        }
        unsigned wbits = __ballot_sync(0xFFFFFFFFu, sup);
        if (lane == 0) row[jw] = wbits;
    }
}

// ---------------------------------------------------------------------------
// Stage 3c: serial greedy scan over sorted order with bitmap suppression.
// One warp per image. Row prefetch (i+1..i+8) hides L2 latency.
// ---------------------------------------------------------------------------
__global__ void __launch_bounds__(32)
scan_kernel(float* __restrict__ out) {
    const int b = blockIdx.x;
    const int lane = threadIdx.x;
    __shared__ uint4 S4[NWORDS / 4];
    if (lane < NWORDS / 4) S4[lane] = make_uint4(0u, 0u, 0u, 0u);
    __syncwarp();
    unsigned* S = (unsigned*)S4;

    const int nvalid = g_nvalid[b];
    const unsigned* mbase = g_mask + (size_t)b * NCAND * NWORDS;
    const int nw = (nvalid + 31) >> 5;
    int picks = 0;

    for (int w = 0; w < nw && picks < MAXDET; ++w) {
        const unsigned lastmask =
            (w == nw - 1 && (nvalid & 31)) ? ((1u << (nvalid & 31)) - 1u)
                                           : 0xFFFFFFFFu;
        unsigned bits = ~S[w] & lastmask;
        while (bits && picks < MAXDET) {
            int bit = __ffs(bits) - 1;
            int i = w * 32 + bit;
            // output pick
            if (lane == 0) {
                int oslot = b * MAXDET + picks;
                float4 bx = g_sbox[b * NCAND + i];
                out[OFF_BOXES + (size_t)oslot * 4 + 0] = bx.x;
                out[OFF_BOXES + (size_t)oslot * 4 + 1] = bx.y;
                out[OFF_BOXES + (size_t)oslot * 4 + 2] = bx.z;
                out[OFF_BOXES + (size_t)oslot * 4 + 3] = bx.w;
                out[OFF_SCORES + oslot] = g_sscore[b * NCAND + i];
                out[OFF_LABELS + oslot] = 0.0f;
                out[OFF_VALID + oslot] = 1.0f;
            }
            picks++;
            // prefetch rows i+1..i+8 into L1 (likely next picks)
            {
                int pr = i + 1 + (lane >> 2);
                if (pr < nvalid) {
                    const unsigned* pp =
                        mbase + (size_t)pr * NWORDS + (lane & 3) * 32;
                    asm volatile("prefetch.global.L1 [%0];" :: "l"(pp));
                }
            }
            // OR row i into suppression bitmap
            if (lane < NWORDS / 4) {
                const uint4* rp = (const uint4*)(mbase + (size_t)i * NWORDS) + lane;
                uint4 r = *rp;
                uint4 s = S4[lane];
                S4[lane] = make_uint4(s.x | r.x, s.y | r.y, s.z | r.z, s.w | r.w);
            }
            __syncwarp();
            bits = ~S[w] & lastmask & ~((2u << bit) - 1u);
        }
    }

    // fill remaining output slots (invalid)
    for (int jt = picks + lane; jt < MAXDET; jt += 32) {
        int oslot = b * MAXDET + jt;
        out[OFF_BOXES + (size_t)oslot * 4 + 0] = 0.0f;
        out[OFF_BOXES + (size_t)oslot * 4 + 1] = 0.0f;
        out[OFF_BOXES + (size_t)oslot * 4 + 2] = 0.0f;
        out[OFF_BOXES + (size_t)oslot * 4 + 3] = 0.0f;
        out[OFF_SCORES + oslot] = 0.0f;
        out[OFF_LABELS + oslot] = -1.0f;
        out[OFF_VALID + oslot] = 0.0f;
    }
}

extern "C" void kernel_launch(void* const* d_in, const int* in_sizes, int n_in,
                              void* d_out, int out_size) {
    const float* points = (const float*)d_in[0];   // (34100, 2)
    const float* gt     = (const float*)d_in[1];   // (8, 200, 4)
    const float* cls    = (const float*)d_in[2];   // (8, 34100, 1)
    const float* reg    = (const float*)d_in[3];   // (8, 34100, 4)
    float* out = (float*)d_out;

    dim3 mg((NPTS + 1023) / 1024, BATCHN);
    match_kernel<<<mg, 256>>>(points, gt, out);
    topk_kernel<<<BATCHN * NLVL, 1024>>>(cls, reg, points);
    sort_kernel<<<BATCHN, 1024>>>();
    dim3 kg((NCAND + 7) / 8, BATCHN);
    mask_kernel<<<kg, 256>>>();
    scan_kernel<<<BATCHN, 32>>>(out);
}

// round 5
// speedup vs baseline: 1.6392x; 1.0052x over previous
#include <cuda_runtime.h>
#include <cstdint>

#define NPTS   34100
#define BATCHN 8
#define NGT    200
#define NLVL   5
#define NCAND  3500
#define MAXDET 300
#define IMGF   1280.0f
#define BIGF   2147483648.0f   // float32(2^31 - 1)
#define NWORDS 112             // row stride in words (110 used, uint4 aligned)
#define NCHUNK 28              // NWORDS/4

// output layout (float32, tuple flattened in return order)
#define OFF_MATCH  0
#define OFF_BOXES  272800
#define OFF_SCORES 282400
#define OFF_LABELS 284800
#define OFF_VALID  287200

__constant__ int c_loff[NLVL]  = {0, 25600, 32000, 33600, 34000};
__constant__ int c_lsize[NLVL] = {25600, 6400, 1600, 400, 100};
__constant__ int c_k[NLVL]     = {1000, 1000, 1000, 400, 100};
__constant__ int c_cbase[NLVL] = {0, 1000, 2000, 3000, 3400};

// scratch (static device globals; no allocation)
__device__ unsigned long long g_keys[BATCHN * NPTS];
__device__ unsigned long long g_ckey[BATCHN * NCAND];
__device__ float  g_cscore[BATCHN * NCAND];
__device__ float4 g_cbox[BATCHN * NCAND];
// sorted-by-key-desc candidate arrays
__device__ float4 g_sbox[BATCHN * NCAND];
__device__ float  g_sscore[BATCHN * NCAND];
__device__ float  g_sarea[BATCHN * NCAND];
__device__ int    g_nvalid[BATCHN];
// suppression bit matrix: row i -> bits over j (sorted order)
__device__ unsigned g_mask[BATCHN * NCAND * NWORDS];

// ---------------------------------------------------------------------------
// Stage 1: point -> gt box matching (argmin of area among containing boxes)
// ---------------------------------------------------------------------------
__global__ void match_kernel(const float* __restrict__ points,
                             const float* __restrict__ gt,
                             float* __restrict__ out) {
    const int b = blockIdx.y;
    __shared__ float4 sbox[NGT];
    __shared__ float  sar[NGT];
    for (int j = threadIdx.x; j < NGT; j += blockDim.x) {
        float4 g = ((const float4*)gt)[b * NGT + j];
        sbox[j] = g;
        sar[j] = (g.z - g.x) * (g.w - g.y);
    }
    __syncthreads();
    int p0 = (blockIdx.x * blockDim.x + threadIdx.x) * 4;   // NPTS % 4 == 0
    if (p0 >= NPTS) return;
    float4 q0 = ((const float4*)points)[(p0 >> 1) + 0];
    float4 q1 = ((const float4*)points)[(p0 >> 1) + 1];
    float px[4] = {q0.x, q0.z, q1.x, q1.z};
    float py[4] = {q0.y, q0.w, q1.y, q1.w};
    float best[4] = {BIGF, BIGF, BIGF, BIGF};
    int bi[4] = {0, 0, 0, 0};
    #pragma unroll 2
    for (int j = 0; j < NGT; ++j) {
        float4 g = sbox[j];
        float ar = sar[j];
        #pragma unroll
        for (int t = 0; t < 4; ++t) {
            bool in = (px[t] >= g.x) && (px[t] <= g.z) &&
                      (py[t] >= g.y) && (py[t] <= g.w);
            float c = in ? ar : BIGF;
            if (c < best[t]) { best[t] = c; bi[t] = j; }  // strict < == first-min
        }
    }
    float* o = out + OFF_MATCH + (size_t)b * NPTS + p0;
    #pragma unroll
    for (int t = 0; t < 4; ++t)
        o[t] = (float)(best[t] < BIGF ? bi[t] : -1);
}

// ---------------------------------------------------------------------------
// Stage 2: exact per-(batch,level) top-k via radix select, 2048 bins/pass
// (11 bits), pass-0 histogram fused into key build, early exit.
// Stable compaction: slot order == global index order (reference tie-break).
// ---------------------------------------------------------------------------
__global__ void __launch_bounds__(1024)
topk_kernel(const float* __restrict__ cls,
            const float* __restrict__ reg,
            const float* __restrict__ points) {
    const int bl = blockIdx.x;
    const int b = bl / NLVL, lvl = bl % NLVL;
    const int loff = c_loff[lvl], n = c_lsize[lvl], k = c_k[lvl];
    const int tid = threadIdx.x;
    const int lane = tid & 31, wid = tid >> 5;
    unsigned long long* keys = g_keys + (size_t)b * NPTS + loff;
    const float* logit = cls + (size_t)b * NPTS + loff;
    const bool sel = (k < n);

    __shared__ int hist[2048];
    __shared__ int s_wt[32], s_wab[32];
    __shared__ unsigned long long s_pref;
    __shared__ int s_remk;
    __shared__ int s_done;

    if (sel) { hist[tid] = 0; hist[tid + 1024] = 0; }
    __syncthreads();

    // phase 1: build keys (+ fused pass-0 histogram)
    for (int i = tid; i < n; i += 1024) {
        float s = 1.0f / (1.0f + expf(-logit[i]));   // sigmoid
        unsigned int u = __float_as_uint(s);
        u = (u & 0x80000000u) ? ~u : (u | 0x80000000u);  // order-preserving
        unsigned long long kk = ((unsigned long long)u << 32) |
                  (unsigned long long)(0xFFFFFFFFu - (unsigned)i);
        keys[i] = kk;
        if (sel) {
            int bin = (int)(kk >> 53);
            unsigned grp = __match_any_sync(__activemask(), bin);
            if ((__ffs(grp) - 1) == lane || !(grp & ((1u << lane) - 1u)))
                if (__popc(grp & ((1u << lane) - 1u)) == 0)
                    atomicAdd(&hist[bin], __popc(grp));
        }
    }
    __syncthreads();

    // phase 2: radix select exact k-th largest key (unique keys)
    unsigned long long prefix = 0ULL;
    if (sel) {
        int remk = k;
        const int iters = (n + 1023) >> 10;
        for (int pass = 0; pass < 6; ++pass) {
            const int shift = (pass < 5) ? (53 - 11 * pass) : 0;
            if (pass > 0) {
                const int prevshift = 53 - 11 * (pass - 1);
                const unsigned long long pmask = (~0ULL) << prevshift;
                hist[tid] = 0; hist[tid + 1024] = 0;
                __syncthreads();
                for (int it = 0; it < iters; ++it) {
                    int i = it * 1024 + tid;
                    bool v = (i < n);
                    unsigned long long kk = v ? keys[i] : 0ULL;
                    int bin = (v && ((kk & pmask) == prefix))
                            ? (int)((kk >> shift) & 2047) : 2048;
                    unsigned grp = __match_any_sync(0xFFFFFFFFu, bin);
                    if (__popc(grp & ((1u << lane) - 1u)) == 0 && bin < 2048)
                        atomicAdd(&hist[bin], __popc(grp));
                }
                __syncthreads();
            }
            // block-parallel selection over 2048 ascending bins
            {
                int c0 = hist[2 * tid], c1 = hist[2 * tid + 1];
                int ps = c0 + c1;
                int sfx = ps;   // suffix-inclusive within warp
                #pragma unroll
                for (int o = 1; o < 32; o <<= 1) {
                    int w = __shfl_down_sync(0xFFFFFFFFu, sfx, o);
                    if (lane + o < 32) sfx += w;
                }
                if (lane == 0) s_wt[wid] = sfx;
                __syncthreads();
                if (wid == 0) {
                    int wt = s_wt[lane];
                    int s = wt;
                    #pragma unroll
                    for (int o = 1; o < 32; o <<= 1) {
                        int w = __shfl_down_sync(0xFFFFFFFFu, s, o);
                        if (lane + o < 32) s += w;
                    }
                    s_wab[lane] = s - wt;   // strictly-above warps
                }
                __syncthreads();
                int above = s_wab[wid] + (sfx - ps);
                if (remk > above && remk <= above + c1) {
                    s_pref = prefix | ((unsigned long long)(2 * tid + 1) << shift);
                    s_remk = remk - above;
                    s_done = (remk - above == c1) ? 1 : 0;
                } else if (remk > above + c1 && remk <= above + ps) {
                    s_pref = prefix | ((unsigned long long)(2 * tid) << shift);
                    s_remk = remk - above - c1;
                    s_done = (remk - above - c1 == c0) ? 1 : 0;
                }
            }
            __syncthreads();
            prefix = s_pref;
            remk = s_remk;
            if (s_done) break;
            __syncthreads();
        }
    }
    // exactly k keys satisfy key >= prefix

    // phase 3: stable compaction (slot order == local index order)
    __shared__ int s_wexcl[32];
    __shared__ int s_total;
    __shared__ int s_base[2];
    if (tid == 0) s_base[0] = 0;
    __syncthreads();
    int par = 0;
    const int citers = (n + 1023) >> 10;
    for (int it = 0; it < citers; ++it) {
        int i = it * 1024 + tid;
        unsigned long long kk = (i < n) ? keys[i] : 0ULL;
        bool pred = (i < n) && (kk >= prefix);
        unsigned ball = __ballot_sync(0xFFFFFFFFu, pred);
        int rank = __popc(ball & ((1u << lane) - 1u));
        if (lane == 0) s_wexcl[wid] = __popc(ball);
        __syncthreads();
        if (wid == 0) {
            int v = s_wexcl[lane];
            int incl = v;
            #pragma unroll
            for (int o = 1; o < 32; o <<= 1) {
                int w = __shfl_up_sync(0xFFFFFFFFu, incl, o);
                if (lane >= o) incl += w;
            }
            s_wexcl[lane] = incl - v;
            if (lane == 31) s_total = incl;
        }
        __syncthreads();
        int base = s_base[par];
        if (pred) {
            int slot = c_cbase[lvl] + base + s_wexcl[wid] + rank;  // image-local
            int gidx = loff + i;
            unsigned int u = (unsigned int)(kk >> 32);
            unsigned int fb = (u & 0x80000000u) ? (u ^ 0x80000000u) : ~u;
            float score = __uint_as_float(fb);
            const float4 rg = ((const float4*)reg)[(size_t)b * NPTS + gidx];
            float2 p = ((const float2*)points)[gidx];
            float l = rg.x * IMGF, t = rg.y * IMGF;
            float r = rg.z * IMGF, bt = rg.w * IMGF;
            float x1 = fminf(fmaxf(p.x - l, 0.0f), IMGF);
            float y1 = fminf(fmaxf(p.y - t, 0.0f), IMGF);
            float x2 = fminf(fmaxf(p.x + r, 0.0f), IMGF);
            float y2 = fminf(fmaxf(p.y + bt, 0.0f), IMGF);
            int ci = b * NCAND + slot;
            g_cscore[ci] = score;
            g_cbox[ci] = make_float4(x1, y1, x2, y2);
            g_ckey[ci] = (score > 0.05f)
                       ? (((unsigned long long)u << 32) |
                          (unsigned long long)(0xFFFFFFFFu - (unsigned)slot))
                       : 0ULL;
        }
        if (tid == 0) s_base[par ^ 1] = base + s_total;
        par ^= 1;
        __syncthreads();
    }
}

// ---------------------------------------------------------------------------
// Stage 3a: per-image bitonic sort (desc) of candidate keys + gather.
// ---------------------------------------------------------------------------
__global__ void __launch_bounds__(1024)
sort_kernel() {
    const int b = blockIdx.x;
    const int tid = threadIdx.x;
    __shared__ unsigned long long sk[4096];
    for (int i = tid; i < 4096; i += 1024)
        sk[i] = (i < NCAND) ? g_ckey[b * NCAND + i] : 0ULL;
    __syncthreads();

    for (int k = 2; k <= 4096; k <<= 1) {
        for (int j = k >> 1; j > 0; j >>= 1) {
            for (int i = tid; i < 4096; i += 1024) {
                int ixj = i ^ j;
                if (ixj > i) {
                    bool up = ((i & k) == 0);
                    unsigned long long a = sk[i], c = sk[ixj];
                    if ((a > c) == up) { sk[i] = c; sk[ixj] = a; }
                }
            }
            __syncthreads();
        }
    }

    __shared__ int s_nv;
    if (tid == 0) s_nv = 0;
    __syncthreads();
    int cnt = 0;
    for (int p = tid; p < NCAND; p += 1024) {
        unsigned long long key = sk[4095 - p];
        if (key) {
            cnt++;
            int slot = (int)(0xFFFFFFFFu - (unsigned)key);
            float4 bx = g_cbox[b * NCAND + slot];
            g_sbox[b * NCAND + p] = bx;
            g_sscore[b * NCAND + p] = g_cscore[b * NCAND + slot];
            g_sarea[b * NCAND + p] = (bx.z - bx.x) * (bx.w - bx.y);
        } else {
            g_sbox[b * NCAND + p] = make_float4(0.f, 0.f, 0.f, 0.f);
            g_sscore[b * NCAND + p] = 0.f;
            g_sarea[b * NCAND + p] = 0.f;
        }
    }
    cnt += __shfl_down_sync(0xFFFFFFFFu, cnt, 16);
    cnt += __shfl_down_sync(0xFFFFFFFFu, cnt, 8);
    cnt += __shfl_down_sync(0xFFFFFFFFu, cnt, 4);
    cnt += __shfl_down_sync(0xFFFFFFFFu, cnt, 2);
    cnt += __shfl_down_sync(0xFFFFFFFFu, cnt, 1);
    if ((tid & 31) == 0) atomicAdd(&s_nv, cnt);
    __syncthreads();
    if (tid == 0) g_nvalid[b] = s_nv;
}

// ---------------------------------------------------------------------------
// exact "fl(inter/denom) > 0.5" without the division on the common path:
//   inter <= 0.5*denom (exact mul)          -> quotient <= 0.5 -> false
//   inter >  denom*0.5000002 (conservative) -> quotient >  0.5+2^-25 -> true
//   else (band width ~4e-7 relative)        -> exact IEEE division
// ---------------------------------------------------------------------------
__device__ __forceinline__ bool iou_gt_half(float inter, float denom) {
    bool sup = inter > 0.5f * denom;
    if (sup && inter <= __fmul_rn(denom, 0.5000002f))
        sup = (inter / denom > 0.5f);
    return sup;
}

// ---------------------------------------------------------------------------
// Stage 3b: suppression bit matrix. One warp per PAIR of sorted rows
// (amortizes j loads); ballot builds the 32-bit word. Words below a row's
// diagonal are left unwritten (provably never observed by the scan).
// ---------------------------------------------------------------------------
__global__ void __launch_bounds__(256)
mask_kernel() {
    const int b = blockIdx.y;
    const int lane = threadIdx.x & 31;
    const int i0 = (blockIdx.x * 8 + (threadIdx.x >> 5)) * 2;
    if (i0 >= NCAND) return;
    const int nv = g_nvalid[b];
    if (i0 >= nv) return;
    const bool two = (i0 + 1 < nv);

    const float4 bA = g_sbox[b * NCAND + i0];
    const float  aA = g_sarea[b * NCAND + i0];
    const float4 bB = two ? g_sbox[b * NCAND + i0 + 1] : bA;
    const float  aB = two ? g_sarea[b * NCAND + i0 + 1] : aA;
    unsigned* rowA = g_mask + ((size_t)(b * NCAND) + i0) * NWORDS;
    unsigned* rowB = rowA + NWORDS;

    const int iw = i0 >> 5;
    for (int jw = iw; jw < NWORDS; ++jw) {
        const int j = jw * 32 + lane;
        float4 bj = make_float4(0.f, 0.f, 0.f, 0.f);
        float aj = 0.f;
        if (j < NCAND) {
            bj = g_sbox[b * NCAND + j];
            aj = g_sarea[b * NCAND + j];
        }
        // row A
        bool supA = false;
        {
            float x1 = fmaxf(bA.x, bj.x), y1 = fmaxf(bA.y, bj.y);
            float x2 = fminf(bA.z, bj.z), y2 = fminf(bA.w, bj.w);
            float inter = fmaxf(x2 - x1, 0.0f) * fmaxf(y2 - y1, 0.0f);
            float denom = ((aA + aj) - inter) + 1e-9f;
            supA = (j > i0) && (j < NCAND) && iou_gt_half(inter, denom);
        }
        unsigned wA = __ballot_sync(0xFFFFFFFFu, supA);
        if (lane == 0) rowA[jw] = wA;
        // row B
        bool supB = false;
        {
            float x1 = fmaxf(bB.x, bj.x), y1 = fmaxf(bB.y, bj.y);
            float x2 = fminf(bB.z, bj.z), y2 = fminf(bB.w, bj.w);
            float inter = fmaxf(x2 - x1, 0.0f) * fmaxf(y2 - y1, 0.0f);
            float denom = ((aB + aj) - inter) + 1e-9f;
            supB = (j > i0 + 1) && (j < NCAND) && iou_gt_half(inter, denom);
        }
        unsigned wB = __ballot_sync(0xFFFFFFFFu, supB);
        if (two && lane == 0) rowB[jw] = wB;
    }
}

// ---------------------------------------------------------------------------
// Stage 3c: serial greedy scan over sorted order with bitmap suppression.
// OR restricted to chunks >= current word; deep prefetch of next 16 rows.
// ---------------------------------------------------------------------------
__global__ void __launch_bounds__(32)
scan_kernel(float* __restrict__ out) {
    const int b = blockIdx.x;
    const int lane = threadIdx.x;
    __shared__ uint4 S4[NCHUNK];
    if (lane < NCHUNK) S4[lane] = make_uint4(0u, 0u, 0u, 0u);
    __syncwarp();
    unsigned* S = (unsigned*)S4;

    const int nvalid = g_nvalid[b];
    const unsigned* mbase = g_mask + (size_t)b * NCAND * NWORDS;
    const int nw = (nvalid + 31) >> 5;
    int picks = 0;

    for (int w = 0; w < nw && picks < MAXDET; ++w) {
        const unsigned lastmask =
            (w == nw - 1 && (nvalid & 31)) ? ((1u << (nvalid & 31)) - 1u)
                                           : 0xFFFFFFFFu;
        const int cw = w >> 2;
        unsigned bits = ~S[w] & lastmask;
        while (bits && picks < MAXDET) {
            int bit = __ffs(bits) - 1;
            int i = w * 32 + bit;
            if (lane == 0) {
                int oslot = b * MAXDET + picks;
                float4 bx = g_sbox[b * NCAND + i];
                out[OFF_BOXES + (size_t)oslot * 4 + 0] = bx.x;
                out[OFF_BOXES + (size_t)oslot * 4 + 1] = bx.y;
                out[OFF_BOXES + (size_t)oslot * 4 + 2] = bx.z;
                out[OFF_BOXES + (size_t)oslot * 4 + 3] = bx.w;
                out[OFF_SCORES + oslot] = g_sscore[b * NCAND + i];
                out[OFF_LABELS + oslot] = 0.0f;
                out[OFF_VALID + oslot] = 1.0f;
            }
            picks++;
            // prefetch live chunk range of rows i+1..i+16
            {
                int pr = i + 1 + (lane >> 1);
                if (pr < nvalid) {
                    const uint4* base = (const uint4*)(mbase + (size_t)pr * NWORDS);
                    for (int c = cw + (lane & 1); c < NCHUNK; c += 2)
                        asm volatile("prefetch.global.L1 [%0];" :: "l"(base + c));
                }
            }
            // OR row i (chunks >= cw; sub-diagonal garbage lands in words
            // the scan has already permanently passed)
            if (lane < NCHUNK && lane >= cw) {
                const uint4* rp = (const uint4*)(mbase + (size_t)i * NWORDS) + lane;
                uint4 r = *rp;
                uint4 s = S4[lane];
                S4[lane] = make_uint4(s.x | r.x, s.y | r.y, s.z | r.z, s.w | r.w);
            }
            __syncwarp();
            bits = ~S[w] & lastmask & ~((2u << bit) - 1u);
        }
    }

    for (int jt = picks + lane; jt < MAXDET; jt += 32) {
        int oslot = b * MAXDET + jt;
        out[OFF_BOXES + (size_t)oslot * 4 + 0] = 0.0f;
        out[OFF_BOXES + (size_t)oslot * 4 + 1] = 0.0f;
        out[OFF_BOXES + (size_t)oslot * 4 + 2] = 0.0f;
        out[OFF_BOXES + (size_t)oslot * 4 + 3] = 0.0f;
        out[OFF_SCORES + oslot] = 0.0f;
        out[OFF_LABELS + oslot] = -1.0f;
        out[OFF_VALID + oslot] = 0.0f;
    }
}

extern "C" void kernel_launch(void* const* d_in, const int* in_sizes, int n_in,
                              void* d_out, int out_size) {
    const float* points = (const float*)d_in[0];   // (34100, 2)
    const float* gt     = (const float*)d_in[1];   // (8, 200, 4)
    const float* cls    = (const float*)d_in[2];   // (8, 34100, 1)
    const float* reg    = (const float*)d_in[3];   // (8, 34100, 4)
    float* out = (float*)d_out;

    // side stream for the independent match_kernel (created on the first,
    // non-captured correctness call; fork-join keeps capture valid)
    static cudaStream_t s2 = nullptr;
    static cudaEvent_t e_fork = nullptr, e_join = nullptr;
    if (s2 == nullptr) {
        cudaStreamCreateWithFlags(&s2, cudaStreamNonBlocking);
        cudaEventCreateWithFlags(&e_fork, cudaEventDisableTiming);
        cudaEventCreateWithFlags(&e_join, cudaEventDisableTiming);
    }

    cudaEventRecord(e_fork, 0);
    cudaStreamWaitEvent(s2, e_fork, 0);

    dim3 mg((NPTS + 1023) / 1024, BATCHN);
    match_kernel<<<mg, 256, 0, s2>>>(points, gt, out);
    cudaEventRecord(e_join, s2);

    topk_kernel<<<BATCHN * NLVL, 1024>>>(cls, reg, points);
    sort_kernel<<<BATCHN, 1024>>>();
    dim3 kg((NCAND / 2 + 7) / 8, BATCHN);
    mask_kernel<<<kg, 256>>>();
    scan_kernel<<<BATCHN, 32>>>(out);

    cudaStreamWaitEvent(0, e_join, 0);
}

// round 6
// speedup vs baseline: 2.0591x; 1.2562x over previous
#include <cuda_runtime.h>
#include <cstdint>

#define NPTS   34100
#define BATCHN 8
#define NGT    200
#define NLVL   5
#define NCAND  3500
#define MAXDET 300
#define IMGF   1280.0f
#define BIGF   2147483648.0f   // float32(2^31 - 1)
#define NWORDS 112             // row stride in words (110 used, uint4 aligned)
#define NCHUNK 28              // NWORDS/4

// output layout (float32, tuple flattened in return order)
#define OFF_MATCH  0
#define OFF_BOXES  272800
#define OFF_SCORES 282400
#define OFF_LABELS 284800
#define OFF_VALID  287200

__constant__ int c_loff[NLVL]  = {0, 25600, 32000, 33600, 34000};
__constant__ int c_lsize[NLVL] = {25600, 6400, 1600, 400, 100};
__constant__ int c_k[NLVL]     = {1000, 1000, 1000, 400, 100};
__constant__ int c_cbase[NLVL] = {0, 1000, 2000, 3000, 3400};

// scratch (static device globals; no allocation)
__device__ unsigned long long g_keys[BATCHN * NPTS];
__device__ unsigned long long g_ckey[BATCHN * NCAND];
__device__ float  g_cscore[BATCHN * NCAND];
__device__ float4 g_cbox[BATCHN * NCAND];
// sorted-by-key-desc candidate arrays
__device__ float4 g_sbox[BATCHN * NCAND];
__device__ float  g_sscore[BATCHN * NCAND];
__device__ float  g_sarea[BATCHN * NCAND];
__device__ int    g_nvalid[BATCHN];
// suppression bit matrix: row i -> bits over j (sorted order)
__device__ unsigned g_mask[BATCHN * NCAND * NWORDS];

// ---------------------------------------------------------------------------
// Stage 1: point -> gt box matching (argmin of area among containing boxes)
// ---------------------------------------------------------------------------
__global__ void match_kernel(const float* __restrict__ points,
                             const float* __restrict__ gt,
                             float* __restrict__ out) {
    const int b = blockIdx.y;
    __shared__ float4 sbox[NGT];
    __shared__ float  sar[NGT];
    for (int j = threadIdx.x; j < NGT; j += blockDim.x) {
        float4 g = ((const float4*)gt)[b * NGT + j];
        sbox[j] = g;
        sar[j] = (g.z - g.x) * (g.w - g.y);
    }
    __syncthreads();
    int p0 = (blockIdx.x * blockDim.x + threadIdx.x) * 4;   // NPTS % 4 == 0
    if (p0 >= NPTS) return;
    float4 q0 = ((const float4*)points)[(p0 >> 1) + 0];
    float4 q1 = ((const float4*)points)[(p0 >> 1) + 1];
    float px[4] = {q0.x, q0.z, q1.x, q1.z};
    float py[4] = {q0.y, q0.w, q1.y, q1.w};
    float best[4] = {BIGF, BIGF, BIGF, BIGF};
    int bi[4] = {0, 0, 0, 0};
    #pragma unroll 2
    for (int j = 0; j < NGT; ++j) {
        float4 g = sbox[j];
        float ar = sar[j];
        #pragma unroll
        for (int t = 0; t < 4; ++t) {
            bool in = (px[t] >= g.x) && (px[t] <= g.z) &&
                      (py[t] >= g.y) && (py[t] <= g.w);
            float c = in ? ar : BIGF;
            if (c < best[t]) { best[t] = c; bi[t] = j; }  // strict < == first-min
        }
    }
    float* o = out + OFF_MATCH + (size_t)b * NPTS + p0;
    #pragma unroll
    for (int t = 0; t < 4; ++t)
        o[t] = (float)(best[t] < BIGF ? bi[t] : -1);
}

// ---------------------------------------------------------------------------
// Stage 2: exact per-(batch,level) top-k via 64-bit radix select on unique
// keys (ordered_score<<32 | ~local_idx); 256 bins, warp-aggregated atomics,
// warp-parallel bin selection, early exit. Stable compaction: slot order ==
// global point-index order (reference tie-break).
// ---------------------------------------------------------------------------
__global__ void __launch_bounds__(1024)
topk_kernel(const float* __restrict__ cls,
            const float* __restrict__ reg,
            const float* __restrict__ points) {
    const int bl = blockIdx.x;
    const int b = bl / NLVL, lvl = bl % NLVL;
    const int loff = c_loff[lvl], n = c_lsize[lvl], k = c_k[lvl];
    const int tid = threadIdx.x;
    const int lane = tid & 31, wid = tid >> 5;
    unsigned long long* keys = g_keys + (size_t)b * NPTS + loff;
    const float* logit = cls + (size_t)b * NPTS + loff;

    for (int i = tid; i < n; i += 1024) {
        float s = 1.0f / (1.0f + expf(-logit[i]));   // sigmoid
        unsigned int u = __float_as_uint(s);
        u = (u & 0x80000000u) ? ~u : (u | 0x80000000u);  // order-preserving
        keys[i] = ((unsigned long long)u << 32) |
                  (unsigned long long)(0xFFFFFFFFu - (unsigned)i);
    }
    __syncthreads();

    unsigned long long prefix = 0ULL;
    if (k < n) {
        __shared__ int hist[256];
        __shared__ unsigned long long s_pref;
        __shared__ int s_remk;
        __shared__ int s_done;
        int remk = k;
        const int iters = (n + 1023) >> 10;
        for (int pass = 0; pass < 8; ++pass) {
            const int shift = 56 - 8 * pass;
            const unsigned long long pmask =
                pass ? (~0ULL << (unsigned)(shift + 8)) : 0ULL;
            if (tid < 256) hist[tid] = 0;
            __syncthreads();
            for (int it = 0; it < iters; ++it) {
                int i = it * 1024 + tid;
                bool v = (i < n);
                unsigned long long kk = v ? keys[i] : 0ULL;
                int bin = (v && ((kk & pmask) == prefix))
                        ? (int)((kk >> shift) & 255) : 256;
                unsigned grp = __match_any_sync(0xFFFFFFFFu, bin);
                int leader = __ffs(grp) - 1;
                if (lane == leader && bin < 256)
                    atomicAdd(&hist[bin], __popc(grp));
            }
            __syncthreads();
            if (wid == 0) {
                int h[8];
                int t8 = 0;
                #pragma unroll
                for (int q = 0; q < 8; ++q) { h[q] = hist[lane * 8 + q]; t8 += h[q]; }
                int psum = t8;
                #pragma unroll
                for (int o = 1; o < 32; o <<= 1) {
                    int w = __shfl_down_sync(0xFFFFFFFFu, psum, o);
                    if (lane + o < 32) psum += w;
                }
                int above = psum - t8;
                if (above < remk && remk <= above + t8) {
                    int r = remk;
                    int c = above;
                    #pragma unroll
                    for (int q = 7; q >= 0; --q) {
                        if (r <= c + h[q]) {
                            s_pref = prefix | ((unsigned long long)(lane * 8 + q) << shift);
                            s_remk = r - c;
                            s_done = (r - c == h[q]) ? 1 : 0;
                            break;
                        }
                        c += h[q];
                    }
                }
            }
            __syncthreads();
            prefix = s_pref;
            remk = s_remk;
            if (s_done) break;
            __syncthreads();
        }
    }
    // exactly k keys satisfy key >= prefix

    // stable compaction (slot order == local index order)
    __shared__ int s_wexcl[32];
    __shared__ int s_total;
    __shared__ int s_base[2];
    if (tid == 0) s_base[0] = 0;
    __syncthreads();
    int par = 0;
    const int citers = (n + 1023) >> 10;
    for (int it = 0; it < citers; ++it) {
        int i = it * 1024 + tid;
        unsigned long long kk = (i < n) ? keys[i] : 0ULL;
        bool pred = (i < n) && (kk >= prefix);
        unsigned ball = __ballot_sync(0xFFFFFFFFu, pred);
        int rank = __popc(ball & ((1u << lane) - 1u));
        if (lane == 0) s_wexcl[wid] = __popc(ball);
        __syncthreads();
        if (wid == 0) {
            int v = s_wexcl[lane];
            int incl = v;
            #pragma unroll
            for (int o = 1; o < 32; o <<= 1) {
                int w = __shfl_up_sync(0xFFFFFFFFu, incl, o);
                if (lane >= o) incl += w;
            }
            s_wexcl[lane] = incl - v;
            if (lane == 31) s_total = incl;
        }
        __syncthreads();
        int base = s_base[par];
        if (pred) {
            int slot = c_cbase[lvl] + base + s_wexcl[wid] + rank;  // image-local
            int gidx = loff + i;
            unsigned int u = (unsigned int)(kk >> 32);
            unsigned int fb = (u & 0x80000000u) ? (u ^ 0x80000000u) : ~u;
            float score = __uint_as_float(fb);
            const float4 rg = ((const float4*)reg)[(size_t)b * NPTS + gidx];
            float2 p = ((const float2*)points)[gidx];
            float l = rg.x * IMGF, t = rg.y * IMGF;
            float r = rg.z * IMGF, bt = rg.w * IMGF;
            float x1 = fminf(fmaxf(p.x - l, 0.0f), IMGF);
            float y1 = fminf(fmaxf(p.y - t, 0.0f), IMGF);
            float x2 = fminf(fmaxf(p.x + r, 0.0f), IMGF);
            float y2 = fminf(fmaxf(p.y + bt, 0.0f), IMGF);
            int ci = b * NCAND + slot;
            g_cscore[ci] = score;
            g_cbox[ci] = make_float4(x1, y1, x2, y2);
            g_ckey[ci] = (score > 0.05f)
                       ? (((unsigned long long)u << 32) |
                          (unsigned long long)(0xFFFFFFFFu - (unsigned)slot))
                       : 0ULL;
        }
        if (tid == 0) s_base[par ^ 1] = base + s_total;
        par ^= 1;
        __syncthreads();
    }
}

// ---------------------------------------------------------------------------
// Stage 3a: per-image bitonic sort (desc) of candidate keys + gather.
// ---------------------------------------------------------------------------
__global__ void __launch_bounds__(1024)
sort_kernel() {
    const int b = blockIdx.x;
    const int tid = threadIdx.x;
    __shared__ unsigned long long sk[4096];
    for (int i = tid; i < 4096; i += 1024)
        sk[i] = (i < NCAND) ? g_ckey[b * NCAND + i] : 0ULL;
    __syncthreads();

    for (int k = 2; k <= 4096; k <<= 1) {
        for (int j = k >> 1; j > 0; j >>= 1) {
            for (int i = tid; i < 4096; i += 1024) {
                int ixj = i ^ j;
                if (ixj > i) {
                    bool up = ((i & k) == 0);
                    unsigned long long a = sk[i], c = sk[ixj];
                    if ((a > c) == up) { sk[i] = c; sk[ixj] = a; }
                }
            }
            __syncthreads();
        }
    }

    __shared__ int s_nv;
    if (tid == 0) s_nv = 0;
    __syncthreads();
    int cnt = 0;
    for (int p = tid; p < NCAND; p += 1024) {
        unsigned long long key = sk[4095 - p];
        if (key) {
            cnt++;
            int slot = (int)(0xFFFFFFFFu - (unsigned)key);
            float4 bx = g_cbox[b * NCAND + slot];
            g_sbox[b * NCAND + p] = bx;
            g_sscore[b * NCAND + p] = g_cscore[b * NCAND + slot];
            g_sarea[b * NCAND + p] = (bx.z - bx.x) * (bx.w - bx.y);
        } else {
            g_sbox[b * NCAND + p] = make_float4(0.f, 0.f, 0.f, 0.f);
            g_sscore[b * NCAND + p] = 0.f;
            g_sarea[b * NCAND + p] = 0.f;
        }
    }
    cnt += __shfl_down_sync(0xFFFFFFFFu, cnt, 16);
    cnt += __shfl_down_sync(0xFFFFFFFFu, cnt, 8);
    cnt += __shfl_down_sync(0xFFFFFFFFu, cnt, 4);
    cnt += __shfl_down_sync(0xFFFFFFFFu, cnt, 2);
    cnt += __shfl_down_sync(0xFFFFFFFFu, cnt, 1);
    if ((tid & 31) == 0) atomicAdd(&s_nv, cnt);
    __syncthreads();
    if (tid == 0) g_nvalid[b] = s_nv;
}

// ---------------------------------------------------------------------------
// exact "fl(inter/denom) > 0.5" without division on the common path:
//   inter <= 0.5*denom            -> quotient <= 0.5          -> false
//   inter >  denom*0.5000002      -> quotient >  0.5 + 2^-25  -> true
//   else (~4e-7 relative band)    -> exact IEEE division
// ---------------------------------------------------------------------------
__device__ __forceinline__ bool iou_gt_half(float inter, float denom) {
    bool sup = inter > 0.5f * denom;
    if (sup && inter <= __fmul_rn(denom, 0.5000002f))
        sup = (inter / denom > 0.5f);
    return sup;
}

// ---------------------------------------------------------------------------
// Stage 3b: suppression bit matrix. One warp per PAIR of sorted rows;
// word loop bounded by nvalid (words past it are never read by the scan).
// ---------------------------------------------------------------------------
__global__ void __launch_bounds__(256)
mask_kernel() {
    const int b = blockIdx.y;
    const int lane = threadIdx.x & 31;
    const int i0 = (blockIdx.x * 8 + (threadIdx.x >> 5)) * 2;
    if (i0 >= NCAND) return;
    const int nv = g_nvalid[b];
    if (i0 >= nv) return;
    const bool two = (i0 + 1 < nv);

    const float4 bA = g_sbox[b * NCAND + i0];
    const float  aA = g_sarea[b * NCAND + i0];
    const float4 bB = two ? g_sbox[b * NCAND + i0 + 1] : bA;
    const float  aB = two ? g_sarea[b * NCAND + i0 + 1] : aA;
    unsigned* rowA = g_mask + ((size_t)(b * NCAND) + i0) * NWORDS;
    unsigned* rowB = rowA + NWORDS;

    const int iw = i0 >> 5;
    const int jwmax = (nv + 31) >> 5;        // scan never reads words >= jwmax
    for (int jw = iw; jw < jwmax; ++jw) {
        const int j = jw * 32 + lane;
        float4 bj = make_float4(0.f, 0.f, 0.f, 0.f);
        float aj = 0.f;
        if (j < NCAND) {
            bj = g_sbox[b * NCAND + j];
            aj = g_sarea[b * NCAND + j];
        }
        bool supA = false;
        {
            float x1 = fmaxf(bA.x, bj.x), y1 = fmaxf(bA.y, bj.y);
            float x2 = fminf(bA.z, bj.z), y2 = fminf(bA.w, bj.w);
            float inter = fmaxf(x2 - x1, 0.0f) * fmaxf(y2 - y1, 0.0f);
            float denom = ((aA + aj) - inter) + 1e-9f;
            supA = (j > i0) && (j < NCAND) && iou_gt_half(inter, denom);
        }
        unsigned wA = __ballot_sync(0xFFFFFFFFu, supA);
        if (lane == 0) rowA[jw] = wA;
        bool supB = false;
        {
            float x1 = fmaxf(bB.x, bj.x), y1 = fmaxf(bB.y, bj.y);
            float x2 = fminf(bB.z, bj.z), y2 = fminf(bB.w, bj.w);
            float inter = fmaxf(x2 - x1, 0.0f) * fmaxf(y2 - y1, 0.0f);
            float denom = ((aB + aj) - inter) + 1e-9f;
            supB = (j > i0 + 1) && (j < NCAND) && iou_gt_half(inter, denom);
        }
        unsigned wB = __ballot_sync(0xFFFFFFFFu, supB);
        if (two && lane == 0) rowB[jw] = wB;
    }
}

// ---------------------------------------------------------------------------
// Stage 3c: serial greedy scan over sorted order with bitmap suppression.
// Light prefetch: rows i+1..i+8, one 128B line per lane (32 prefetches/pick).
// ---------------------------------------------------------------------------
__global__ void __launch_bounds__(32)
scan_kernel(float* __restrict__ out) {
    const int b = blockIdx.x;
    const int lane = threadIdx.x;
    __shared__ uint4 S4[NCHUNK];
    if (lane < NCHUNK) S4[lane] = make_uint4(0u, 0u, 0u, 0u);
    __syncwarp();
    unsigned* S = (unsigned*)S4;

    const int nvalid = g_nvalid[b];
    const unsigned* mbase = g_mask + (size_t)b * NCAND * NWORDS;
    const int nw = (nvalid + 31) >> 5;
    const int nchunk = (nw + 3) >> 2;        // live chunk count
    int picks = 0;

    for (int w = 0; w < nw && picks < MAXDET; ++w) {
        const unsigned lastmask =
            (w == nw - 1 && (nvalid & 31)) ? ((1u << (nvalid & 31)) - 1u)
                                           : 0xFFFFFFFFu;
        const int cw = w >> 2;
        unsigned bits = ~S[w] & lastmask;
        while (bits && picks < MAXDET) {
            int bit = __ffs(bits) - 1;
            int i = w * 32 + bit;
            if (lane == 0) {
                int oslot = b * MAXDET + picks;
                float4 bx = g_sbox[b * NCAND + i];
                out[OFF_BOXES + (size_t)oslot * 4 + 0] = bx.x;
                out[OFF_BOXES + (size_t)oslot * 4 + 1] = bx.y;
                out[OFF_BOXES + (size_t)oslot * 4 + 2] = bx.z;
                out[OFF_BOXES + (size_t)oslot * 4 + 3] = bx.w;
                out[OFF_SCORES + oslot] = g_sscore[b * NCAND + i];
                out[OFF_LABELS + oslot] = 0.0f;
                out[OFF_VALID + oslot] = 1.0f;
            }
            picks++;
            // prefetch rows i+1..i+8 (one 128B line per lane)
            {
                int pr = i + 1 + (lane >> 2);
                if (pr < nvalid) {
                    const unsigned* pp =
                        mbase + (size_t)pr * NWORDS + (lane & 3) * 32;
                    asm volatile("prefetch.global.L1 [%0];" :: "l"(pp));
                }
            }
            // OR row i (live chunks >= cw; sub-diagonal garbage lands in
            // words the scan has already permanently passed)
            if (lane >= cw && lane < nchunk) {
                const uint4* rp = (const uint4*)(mbase + (size_t)i * NWORDS) + lane;
                uint4 r = *rp;
                uint4 s = S4[lane];
                S4[lane] = make_uint4(s.x | r.x, s.y | r.y, s.z | r.z, s.w | r.w);
            }
            __syncwarp();
            bits = ~S[w] & lastmask & ~((2u << bit) - 1u);
        }
    }

    for (int jt = picks + lane; jt < MAXDET; jt += 32) {
        int oslot = b * MAXDET + jt;
        out[OFF_BOXES + (size_t)oslot * 4 + 0] = 0.0f;
        out[OFF_BOXES + (size_t)oslot * 4 + 1] = 0.0f;
        out[OFF_BOXES + (size_t)oslot * 4 + 2] = 0.0f;
        out[OFF_BOXES + (size_t)oslot * 4 + 3] = 0.0f;
        out[OFF_SCORES + oslot] = 0.0f;
        out[OFF_LABELS + oslot] = -1.0f;
        out[OFF_VALID + oslot] = 0.0f;
    }
}

extern "C" void kernel_launch(void* const* d_in, const int* in_sizes, int n_in,
                              void* d_out, int out_size) {
    const float* points = (const float*)d_in[0];   // (34100, 2)
    const float* gt     = (const float*)d_in[1];   // (8, 200, 4)
    const float* cls    = (const float*)d_in[2];   // (8, 34100, 1)
    const float* reg    = (const float*)d_in[3];   // (8, 34100, 4)
    float* out = (float*)d_out;

    // side stream for the independent match_kernel (created on the first,
    // non-captured correctness call; fork-join keeps capture valid)
    static cudaStream_t s2 = nullptr;
    static cudaEvent_t e_fork = nullptr, e_join = nullptr;
    if (s2 == nullptr) {
        cudaStreamCreateWithFlags(&s2, cudaStreamNonBlocking);
        cudaEventCreateWithFlags(&e_fork, cudaEventDisableTiming);
        cudaEventCreateWithFlags(&e_join, cudaEventDisableTiming);
    }

    cudaEventRecord(e_fork, 0);
    cudaStreamWaitEvent(s2, e_fork, 0);

    dim3 mg((NPTS + 1023) / 1024, BATCHN);
    match_kernel<<<mg, 256, 0, s2>>>(points, gt, out);
    cudaEventRecord(e_join, s2);

    topk_kernel<<<BATCHN * NLVL, 1024>>>(cls, reg, points);
    sort_kernel<<<BATCHN, 1024>>>();
    dim3 kg((NCAND / 2 + 7) / 8, BATCHN);
    mask_kernel<<<kg, 256>>>();
    scan_kernel<<<BATCHN, 32>>>(out);

    cudaStreamWaitEvent(0, e_join, 0);
}

// round 7
// speedup vs baseline: 2.1257x; 1.0324x over previous
#include <cuda_runtime.h>
#include <cstdint>

#define NPTS   34100
#define BATCHN 8
#define NGT    200
#define NLVL   5
#define NCAND  3500
#define MAXDET 300
#define IMGF   1280.0f
#define BIGF   2147483648.0f   // float32(2^31 - 1)
#define NWORDS 112             // row stride in words (110 used, uint4 aligned)
#define NCHUNK 28              // NWORDS/4

// output layout (float32, tuple flattened in return order)
#define OFF_MATCH  0
#define OFF_BOXES  272800
#define OFF_SCORES 282400
#define OFF_LABELS 284800
#define OFF_VALID  287200

__constant__ int c_loff[NLVL]  = {0, 25600, 32000, 33600, 34000};
__constant__ int c_lsize[NLVL] = {25600, 6400, 1600, 400, 100};
__constant__ int c_k[NLVL]     = {1000, 1000, 1000, 400, 100};
__constant__ int c_cbase[NLVL] = {0, 1000, 2000, 3000, 3400};

// scratch (static device globals; no allocation)
__device__ unsigned long long g_keys[BATCHN * NPTS];
__device__ unsigned long long g_ckey[BATCHN * NCAND];
__device__ float  g_cscore[BATCHN * NCAND];
__device__ float4 g_cbox[BATCHN * NCAND];
// sorted-by-key-desc candidate arrays
__device__ float4 g_sbox[BATCHN * NCAND];
__device__ float  g_sscore[BATCHN * NCAND];
__device__ float  g_sarea[BATCHN * NCAND];
__device__ int    g_nvalid[BATCHN];
// suppression bit matrix: row i -> bits over j (sorted order)
__device__ unsigned g_mask[BATCHN * NCAND * NWORDS];

// ---------------------------------------------------------------------------
// Stage 1: point -> gt box matching (argmin of area among containing boxes)
// ---------------------------------------------------------------------------
__global__ void match_kernel(const float* __restrict__ points,
                             const float* __restrict__ gt,
                             float* __restrict__ out) {
    const int b = blockIdx.y;
    __shared__ float4 sbox[NGT];
    __shared__ float  sar[NGT];
    for (int j = threadIdx.x; j < NGT; j += blockDim.x) {
        float4 g = ((const float4*)gt)[b * NGT + j];
        sbox[j] = g;
        sar[j] = (g.z - g.x) * (g.w - g.y);
    }
    __syncthreads();
    int p0 = (blockIdx.x * blockDim.x + threadIdx.x) * 4;   // NPTS % 4 == 0
    if (p0 >= NPTS) return;
    float4 q0 = ((const float4*)points)[(p0 >> 1) + 0];
    float4 q1 = ((const float4*)points)[(p0 >> 1) + 1];
    float px[4] = {q0.x, q0.z, q1.x, q1.z};
    float py[4] = {q0.y, q0.w, q1.y, q1.w};
    float best[4] = {BIGF, BIGF, BIGF, BIGF};
    int bi[4] = {0, 0, 0, 0};
    #pragma unroll 2
    for (int j = 0; j < NGT; ++j) {
        float4 g = sbox[j];
        float ar = sar[j];
        #pragma unroll
        for (int t = 0; t < 4; ++t) {
            bool in = (px[t] >= g.x) && (px[t] <= g.z) &&
                      (py[t] >= g.y) && (py[t] <= g.w);
            float c = in ? ar : BIGF;
            if (c < best[t]) { best[t] = c; bi[t] = j; }  // strict < == first-min
        }
    }
    float* o = out + OFF_MATCH + (size_t)b * NPTS + p0;
    #pragma unroll
    for (int t = 0; t < 4; ++t)
        o[t] = (float)(best[t] < BIGF ? bi[t] : -1);
}

// ---------------------------------------------------------------------------
// Stage 2: exact per-(batch,level) top-k via 64-bit radix select on unique
// keys (ordered_score<<32 | ~local_idx); 256 bins, warp-aggregated atomics,
// warp-parallel bin selection, early exit. Stable compaction: slot order ==
// global point-index order (reference tie-break).
// ---------------------------------------------------------------------------
__global__ void __launch_bounds__(1024)
topk_kernel(const float* __restrict__ cls,
            const float* __restrict__ reg,
            const float* __restrict__ points) {
    const int bl = blockIdx.x;
    const int b = bl / NLVL, lvl = bl % NLVL;
    const int loff = c_loff[lvl], n = c_lsize[lvl], k = c_k[lvl];
    const int tid = threadIdx.x;
    const int lane = tid & 31, wid = tid >> 5;
    unsigned long long* keys = g_keys + (size_t)b * NPTS + loff;
    const float* logit = cls + (size_t)b * NPTS + loff;

    for (int i = tid; i < n; i += 1024) {
        float s = 1.0f / (1.0f + expf(-logit[i]));   // sigmoid
        unsigned int u = __float_as_uint(s);
        u = (u & 0x80000000u) ? ~u : (u | 0x80000000u);  // order-preserving
        keys[i] = ((unsigned long long)u << 32) |
                  (unsigned long long)(0xFFFFFFFFu - (unsigned)i);
    }
    __syncthreads();

    unsigned long long prefix = 0ULL;
    if (k < n) {
        __shared__ int hist[256];
        __shared__ unsigned long long s_pref;
        __shared__ int s_remk;
        __shared__ int s_done;
        int remk = k;
        const int iters = (n + 1023) >> 10;
        for (int pass = 0; pass < 8; ++pass) {
            const int shift = 56 - 8 * pass;
            const unsigned long long pmask =
                pass ? (~0ULL << (unsigned)(shift + 8)) : 0ULL;
            if (tid < 256) hist[tid] = 0;
            __syncthreads();
            for (int it = 0; it < iters; ++it) {
                int i = it * 1024 + tid;
                bool v = (i < n);
                unsigned long long kk = v ? keys[i] : 0ULL;
                int bin = (v && ((kk & pmask) == prefix))
                        ? (int)((kk >> shift) & 255) : 256;
                unsigned grp = __match_any_sync(0xFFFFFFFFu, bin);
                int leader = __ffs(grp) - 1;
                if (lane == leader && bin < 256)
                    atomicAdd(&hist[bin], __popc(grp));
            }
            __syncthreads();
            if (wid == 0) {
                int h[8];
                int t8 = 0;
                #pragma unroll
                for (int q = 0; q < 8; ++q) { h[q] = hist[lane * 8 + q]; t8 += h[q]; }
                int psum = t8;
                #pragma unroll
                for (int o = 1; o < 32; o <<= 1) {
                    int w = __shfl_down_sync(0xFFFFFFFFu, psum, o);
                    if (lane + o < 32) psum += w;
                }
                int above = psum - t8;
                if (above < remk && remk <= above + t8) {
                    int r = remk;
                    int c = above;
                    #pragma unroll
                    for (int q = 7; q >= 0; --q) {
                        if (r <= c + h[q]) {
                            s_pref = prefix | ((unsigned long long)(lane * 8 + q) << shift);
                            s_remk = r - c;
                            s_done = (r - c == h[q]) ? 1 : 0;
                            break;
                        }
                        c += h[q];
                    }
                }
            }
            __syncthreads();
            prefix = s_pref;
            remk = s_remk;
            if (s_done) break;
            __syncthreads();
        }
    }
    // exactly k keys satisfy key >= prefix

    // stable compaction (slot order == local index order)
    __shared__ int s_wexcl[32];
    __shared__ int s_total;
    __shared__ int s_base[2];
    if (tid == 0) s_base[0] = 0;
    __syncthreads();
    int par = 0;
    const int citers = (n + 1023) >> 10;
    for (int it = 0; it < citers; ++it) {
        int i = it * 1024 + tid;
        unsigned long long kk = (i < n) ? keys[i] : 0ULL;
        bool pred = (i < n) && (kk >= prefix);
        unsigned ball = __ballot_sync(0xFFFFFFFFu, pred);
        int rank = __popc(ball & ((1u << lane) - 1u));
        if (lane == 0) s_wexcl[wid] = __popc(ball);
        __syncthreads();
        if (wid == 0) {
            int v = s_wexcl[lane];
            int incl = v;
            #pragma unroll
            for (int o = 1; o < 32; o <<= 1) {
                int w = __shfl_up_sync(0xFFFFFFFFu, incl, o);
                if (lane >= o) incl += w;
            }
            s_wexcl[lane] = incl - v;
            if (lane == 31) s_total = incl;
        }
        __syncthreads();
        int base = s_base[par];
        if (pred) {
            int slot = c_cbase[lvl] + base + s_wexcl[wid] + rank;  // image-local
            int gidx = loff + i;
            unsigned int u = (unsigned int)(kk >> 32);
            unsigned int fb = (u & 0x80000000u) ? (u ^ 0x80000000u) : ~u;
            float score = __uint_as_float(fb);
            const float4 rg = ((const float4*)reg)[(size_t)b * NPTS + gidx];
            float2 p = ((const float2*)points)[gidx];
            float l = rg.x * IMGF, t = rg.y * IMGF;
            float r = rg.z * IMGF, bt = rg.w * IMGF;
            float x1 = fminf(fmaxf(p.x - l, 0.0f), IMGF);
            float y1 = fminf(fmaxf(p.y - t, 0.0f), IMGF);
            float x2 = fminf(fmaxf(p.x + r, 0.0f), IMGF);
            float y2 = fminf(fmaxf(p.y + bt, 0.0f), IMGF);
            int ci = b * NCAND + slot;
            g_cscore[ci] = score;
            g_cbox[ci] = make_float4(x1, y1, x2, y2);
            g_ckey[ci] = (score > 0.05f)
                       ? (((unsigned long long)u << 32) |
                          (unsigned long long)(0xFFFFFFFFu - (unsigned)slot))
                       : 0ULL;
        }
        if (tid == 0) s_base[par ^ 1] = base + s_total;
        par ^= 1;
        __syncthreads();
    }
}

// ---------------------------------------------------------------------------
// Stage 3a: per-image bitonic sort (desc) of candidate keys + gather.
// Exchange distance j<32 stays inside one warp's 32-element group, so block
// barriers are only needed when the stage or its successor crosses warps.
// ---------------------------------------------------------------------------
__global__ void __launch_bounds__(1024)
sort_kernel() {
    const int b = blockIdx.x;
    const int tid = threadIdx.x;
    __shared__ unsigned long long sk[4096];
    for (int i = tid; i < 4096; i += 1024)
        sk[i] = (i < NCAND) ? g_ckey[b * NCAND + i] : 0ULL;
    __syncthreads();

    for (int k = 2; k <= 4096; k <<= 1) {
        for (int j = k >> 1; j > 0; j >>= 1) {
            for (int i = tid; i < 4096; i += 1024) {
                int ixj = i ^ j;
                if (ixj > i) {
                    bool up = ((i & k) == 0);
                    unsigned long long a = sk[i], c = sk[ixj];
                    if ((a > c) == up) { sk[i] = c; sk[ixj] = a; }
                }
            }
            int jnext = (j > 1) ? (j >> 1) : k;   // next k's first stage j == k
            if (j >= 32 || jnext >= 32) __syncthreads();
            else                        __syncwarp();
        }
    }

    __shared__ int s_nv;
    if (tid == 0) s_nv = 0;
    __syncthreads();
    int cnt = 0;
    for (int p = tid; p < NCAND; p += 1024) {
        unsigned long long key = sk[4095 - p];
        if (key) {
            cnt++;
            int slot = (int)(0xFFFFFFFFu - (unsigned)key);
            float4 bx = g_cbox[b * NCAND + slot];
            g_sbox[b * NCAND + p] = bx;
            g_sscore[b * NCAND + p] = g_cscore[b * NCAND + slot];
            g_sarea[b * NCAND + p] = (bx.z - bx.x) * (bx.w - bx.y);
        } else {
            g_sbox[b * NCAND + p] = make_float4(0.f, 0.f, 0.f, 0.f);
            g_sscore[b * NCAND + p] = 0.f;
            g_sarea[b * NCAND + p] = 0.f;
        }
    }
    cnt += __shfl_down_sync(0xFFFFFFFFu, cnt, 16);
    cnt += __shfl_down_sync(0xFFFFFFFFu, cnt, 8);
    cnt += __shfl_down_sync(0xFFFFFFFFu, cnt, 4);
    cnt += __shfl_down_sync(0xFFFFFFFFu, cnt, 2);
    cnt += __shfl_down_sync(0xFFFFFFFFu, cnt, 1);
    if ((tid & 31) == 0) atomicAdd(&s_nv, cnt);
    __syncthreads();
    if (tid == 0) g_nvalid[b] = s_nv;
}

// ---------------------------------------------------------------------------
// exact "fl(inter/denom) > 0.5" without division on the common path:
//   inter <= 0.5*denom            -> quotient <= 0.5          -> false
//   inter >  denom*0.5000002      -> quotient >  0.5 + 2^-25  -> true
//   else (~4e-7 relative band)    -> exact IEEE division
// ---------------------------------------------------------------------------
__device__ __forceinline__ bool iou_gt_half(float inter, float denom) {
    bool sup = inter > 0.5f * denom;
    if (sup && inter <= __fmul_rn(denom, 0.5000002f))
        sup = (inter / denom > 0.5f);
    return sup;
}

// ---------------------------------------------------------------------------
// Stage 3b: suppression bit matrix. One warp per 4 sorted rows (amortizes
// the j-side loads over 4 IoUs); word loop bounded by nvalid.
// ---------------------------------------------------------------------------
__global__ void __launch_bounds__(256)
mask_kernel() {
    const int b = blockIdx.y;
    const int lane = threadIdx.x & 31;
    const int i0 = (blockIdx.x * 8 + (threadIdx.x >> 5)) * 4;
    const int nv = g_nvalid[b];
    if (i0 >= nv) return;
    const int nr = min(4, nv - i0);

    float4 bi[4];
    float  ai[4];
    #pragma unroll
    for (int r = 0; r < 4; ++r) {
        int ii = i0 + ((r < nr) ? r : 0);
        bi[r] = g_sbox[b * NCAND + ii];
        ai[r] = g_sarea[b * NCAND + ii];
    }
    unsigned* rowbase = g_mask + ((size_t)(b * NCAND) + i0) * NWORDS;

    const int iw = i0 >> 5;
    const int jwmax = (nv + 31) >> 5;        // scan never reads words >= jwmax
    for (int jw = iw; jw < jwmax; ++jw) {
        const int j = jw * 32 + lane;
        float4 bj = make_float4(0.f, 0.f, 0.f, 0.f);
        float aj = 0.f;
        if (j < NCAND) {
            bj = g_sbox[b * NCAND + j];
            aj = g_sarea[b * NCAND + j];
        }
        #pragma unroll
        for (int r = 0; r < 4; ++r) {
            float x1 = fmaxf(bi[r].x, bj.x), y1 = fmaxf(bi[r].y, bj.y);
            float x2 = fminf(bi[r].z, bj.z), y2 = fminf(bi[r].w, bj.w);
            float inter = fmaxf(x2 - x1, 0.0f) * fmaxf(y2 - y1, 0.0f);
            float denom = ((ai[r] + aj) - inter) + 1e-9f;
            bool sup = (j > i0 + r) && (j < NCAND) && iou_gt_half(inter, denom);
            unsigned wbits = __ballot_sync(0xFFFFFFFFu, sup);
            if (lane == 0 && r < nr) rowbase[(size_t)r * NWORDS + jw] = wbits;
        }
    }
}

// ---------------------------------------------------------------------------
// Stage 3c: serial greedy scan over sorted order with bitmap suppression.
// Targeted prefetch: lanes 0-7 find the first live bit in words w..w+7 of
// the CURRENT alive bitmap and prefetch those exact rows before the OR.
// ---------------------------------------------------------------------------
__global__ void __launch_bounds__(32)
scan_kernel(float* __restrict__ out) {
    const int b = blockIdx.x;
    const int lane = threadIdx.x;
    __shared__ uint4 S4[NCHUNK];
    if (lane < NCHUNK) S4[lane] = make_uint4(0u, 0u, 0u, 0u);
    __syncwarp();
    unsigned* S = (unsigned*)S4;

    const int nvalid = g_nvalid[b];
    const unsigned* mbase = g_mask + (size_t)b * NCAND * NWORDS;
    const int nw = (nvalid + 31) >> 5;
    const int nchunk = (nw + 3) >> 2;        // live chunk count
    const unsigned tailmask = (nvalid & 31) ? ((1u << (nvalid & 31)) - 1u)
                                            : 0xFFFFFFFFu;
    int picks = 0;

    for (int w = 0; w < nw && picks < MAXDET; ++w) {
        const unsigned lastmask = (w == nw - 1) ? tailmask : 0xFFFFFFFFu;
        const int cw = w >> 2;
        unsigned bits = ~S[w] & lastmask;
        while (bits && picks < MAXDET) {
            int bit = __ffs(bits) - 1;
            int i = w * 32 + bit;
            const unsigned above = ~((2u << bit) - 1u);

            // targeted prefetch: first live bit of words w..w+7 (pre-OR view)
            {
                int wl = w + lane;
                if (lane < 8 && wl < nw) {
                    unsigned bl;
                    if (lane == 0) bl = bits & above;
                    else {
                        bl = ~S[wl];
                        if (wl == nw - 1) bl &= tailmask;
                    }
                    if (bl) {
                        int pr = wl * 32 + (__ffs(bl) - 1);
                        const char* pp = (const char*)(mbase +
                            (size_t)pr * NWORDS + cw * 4);
                        asm volatile("prefetch.global.L1 [%0];" :: "l"(pp));
                        asm volatile("prefetch.global.L1 [%0];" :: "l"(pp + 128));
                        asm volatile("prefetch.global.L1 [%0];" :: "l"(pp + 256));
                        asm volatile("prefetch.global.L1 [%0];" :: "l"(pp + 384));
                    }
                }
            }

            // load row i chunks (issued before output writes)
            const bool doOR = (lane >= cw && lane < nchunk);
            uint4 r = make_uint4(0u, 0u, 0u, 0u);
            if (doOR)
                r = *((const uint4*)(mbase + (size_t)i * NWORDS) + lane);

            if (lane == 0) {
                int oslot = b * MAXDET + picks;
                float4 bx = g_sbox[b * NCAND + i];
                out[OFF_BOXES + (size_t)oslot * 4 + 0] = bx.x;
                out[OFF_BOXES + (size_t)oslot * 4 + 1] = bx.y;
                out[OFF_BOXES + (size_t)oslot * 4 + 2] = bx.z;
                out[OFF_BOXES + (size_t)oslot * 4 + 3] = bx.w;
                out[OFF_SCORES + oslot] = g_sscore[b * NCAND + i];
                out[OFF_LABELS + oslot] = 0.0f;
                out[OFF_VALID + oslot] = 1.0f;
            }
            picks++;

            if (doOR) {
                uint4 s = S4[lane];
                S4[lane] = make_uint4(s.x | r.x, s.y | r.y, s.z | r.z, s.w | r.w);
            }
            __syncwarp();
            bits = ~S[w] & lastmask & above;
        }
    }

    for (int jt = picks + lane; jt < MAXDET; jt += 32) {
        int oslot = b * MAXDET + jt;
        out[OFF_BOXES + (size_t)oslot * 4 + 0] = 0.0f;
        out[OFF_BOXES + (size_t)oslot * 4 + 1] = 0.0f;
        out[OFF_BOXES + (size_t)oslot * 4 + 2] = 0.0f;
        out[OFF_BOXES + (size_t)oslot * 4 + 3] = 0.0f;
        out[OFF_SCORES + oslot] = 0.0f;
        out[OFF_LABELS + oslot] = -1.0f;
        out[OFF_VALID + oslot] = 0.0f;
    }
}

extern "C" void kernel_launch(void* const* d_in, const int* in_sizes, int n_in,
                              void* d_out, int out_size) {
    const float* points = (const float*)d_in[0];   // (34100, 2)
    const float* gt     = (const float*)d_in[1];   // (8, 200, 4)
    const float* cls    = (const float*)d_in[2];   // (8, 34100, 1)
    const float* reg    = (const float*)d_in[3];   // (8, 34100, 4)
    float* out = (float*)d_out;

    // side stream for the independent match_kernel (created on the first,
    // non-captured correctness call; fork-join keeps capture valid)
    static cudaStream_t s2 = nullptr;
    static cudaEvent_t e_fork = nullptr, e_join = nullptr;
    if (s2 == nullptr) {
        cudaStreamCreateWithFlags(&s2, cudaStreamNonBlocking);
        cudaEventCreateWithFlags(&e_fork, cudaEventDisableTiming);
        cudaEventCreateWithFlags(&e_join, cudaEventDisableTiming);
    }

    cudaEventRecord(e_fork, 0);
    cudaStreamWaitEvent(s2, e_fork, 0);

    dim3 mg((NPTS + 1023) / 1024, BATCHN);
    match_kernel<<<mg, 256, 0, s2>>>(points, gt, out);
    cudaEventRecord(e_join, s2);

    topk_kernel<<<BATCHN * NLVL, 1024>>>(cls, reg, points);
    sort_kernel<<<BATCHN, 1024>>>();
    dim3 kg((NCAND / 4 + 7) / 8, BATCHN);
    mask_kernel<<<kg, 256>>>();
    scan_kernel<<<BATCHN, 32>>>(out);

    cudaStreamWaitEvent(0, e_join, 0);
}

// round 9
// speedup vs baseline: 2.1963x; 1.0332x over previous
#include <cuda_runtime.h>
#include <cstdint>

#define NPTS   34100
#define BATCHN 8
#define NGT    200
#define NLVL   5
#define NCAND  3500
#define MAXDET 300
#define IMGF   1280.0f
#define BIGF   2147483648.0f   // float32(2^31 - 1)
#define NWORDS 112             // row stride in words (110 used, uint4 aligned)
#define NCHUNK 28              // NWORDS/4
#define HALF   4               // images per stream pipeline

// output layout (float32, tuple flattened in return order)
#define OFF_MATCH  0
#define OFF_BOXES  272800
#define OFF_SCORES 282400
#define OFF_LABELS 284800
#define OFF_VALID  287200

__constant__ int c_loff[NLVL]  = {0, 25600, 32000, 33600, 34000};
__constant__ int c_lsize[NLVL] = {25600, 6400, 1600, 400, 100};
__constant__ int c_k[NLVL]     = {1000, 1000, 1000, 400, 100};
__constant__ int c_cbase[NLVL] = {0, 1000, 2000, 3000, 3400};

// scratch (static device globals; no allocation)
__device__ unsigned long long g_keys[BATCHN * NPTS];
__device__ unsigned long long g_ckey[BATCHN * NCAND];
__device__ float  g_cscore[BATCHN * NCAND];
__device__ float4 g_cbox[BATCHN * NCAND];
// sorted-by-key-desc candidate arrays
__device__ float4 g_sbox[BATCHN * NCAND];
__device__ float  g_sscore[BATCHN * NCAND];
__device__ float  g_sarea[BATCHN * NCAND];
__device__ int    g_nvalid[BATCHN];
// suppression bit matrix: row i -> bits over j (sorted order)
__device__ unsigned g_mask[BATCHN * NCAND * NWORDS];

// ---------------------------------------------------------------------------
// Stage 1: point -> gt box matching (argmin of area among containing boxes)
// ---------------------------------------------------------------------------
__global__ void match_kernel(const float* __restrict__ points,
                             const float* __restrict__ gt,
                             float* __restrict__ out, int b0) {
    const int b = b0 + blockIdx.y;
    __shared__ float4 sbox[NGT];
    __shared__ float  sar[NGT];
    for (int j = threadIdx.x; j < NGT; j += blockDim.x) {
        float4 g = ((const float4*)gt)[b * NGT + j];
        sbox[j] = g;
        sar[j] = (g.z - g.x) * (g.w - g.y);
    }
    __syncthreads();
    int p0 = (blockIdx.x * blockDim.x + threadIdx.x) * 4;   // NPTS % 4 == 0
    if (p0 >= NPTS) return;
    float4 q0 = ((const float4*)points)[(p0 >> 1) + 0];
    float4 q1 = ((const float4*)points)[(p0 >> 1) + 1];
    float px[4] = {q0.x, q0.z, q1.x, q1.z};
    float py[4] = {q0.y, q0.w, q1.y, q1.w};
    float best[4] = {BIGF, BIGF, BIGF, BIGF};
    int bi[4] = {0, 0, 0, 0};
    #pragma unroll 2
    for (int j = 0; j < NGT; ++j) {
        float4 g = sbox[j];
        float ar = sar[j];
        #pragma unroll
        for (int t = 0; t < 4; ++t) {
            bool in = (px[t] >= g.x) && (px[t] <= g.z) &&
                      (py[t] >= g.y) && (py[t] <= g.w);
            float c = in ? ar : BIGF;
            if (c < best[t]) { best[t] = c; bi[t] = j; }  // strict < == first-min
        }
    }
    float* o = out + OFF_MATCH + (size_t)b * NPTS + p0;
    #pragma unroll
    for (int t = 0; t < 4; ++t)
        o[t] = (float)(best[t] < BIGF ? bi[t] : -1);
}

// ---------------------------------------------------------------------------
// Stage 2: exact per-(image,level) top-k via 64-bit radix select on unique
// keys (ordered_score<<32 | ~local_idx); 256 bins, warp-aggregated atomics,
// early exit. Compaction: contiguous-chunk stable (2 barriers total).
// ---------------------------------------------------------------------------
__global__ void __launch_bounds__(1024)
topk_kernel(const float* __restrict__ cls,
            const float* __restrict__ reg,
            const float* __restrict__ points, int b0) {
    const int lvl = blockIdx.x;
    const int b = b0 + blockIdx.y;
    const int loff = c_loff[lvl], n = c_lsize[lvl], k = c_k[lvl];
    const int tid = threadIdx.x;
    const int lane = tid & 31, wid = tid >> 5;
    unsigned long long* keys = g_keys + (size_t)b * NPTS + loff;
    const float* logit = cls + (size_t)b * NPTS + loff;

    for (int i = tid; i < n; i += 1024) {
        float s = 1.0f / (1.0f + expf(-logit[i]));   // sigmoid
        unsigned int u = __float_as_uint(s);
        u = (u & 0x80000000u) ? ~u : (u | 0x80000000u);  // order-preserving
        keys[i] = ((unsigned long long)u << 32) |
                  (unsigned long long)(0xFFFFFFFFu - (unsigned)i);
    }
    __syncthreads();

    unsigned long long prefix = 0ULL;
    if (k < n) {
        __shared__ int hist[256];
        __shared__ unsigned long long s_pref;
        __shared__ int s_remk;
        __shared__ int s_done;
        int remk = k;
        const int iters = (n + 1023) >> 10;
        for (int pass = 0; pass < 8; ++pass) {
            const int shift = 56 - 8 * pass;
            const unsigned long long pmask =
                pass ? (~0ULL << (unsigned)(shift + 8)) : 0ULL;
            if (tid < 256) hist[tid] = 0;
            __syncthreads();
            for (int it = 0; it < iters; ++it) {
                int i = it * 1024 + tid;
                bool v = (i < n);
                unsigned long long kk = v ? keys[i] : 0ULL;
                int bin = (v && ((kk & pmask) == prefix))
                        ? (int)((kk >> shift) & 255) : 256;
                unsigned grp = __match_any_sync(0xFFFFFFFFu, bin);
                int leader = __ffs(grp) - 1;
                if (lane == leader && bin < 256)
                    atomicAdd(&hist[bin], __popc(grp));
            }
            __syncthreads();
            if (wid == 0) {
                int h[8];
                int t8 = 0;
                #pragma unroll
                for (int q = 0; q < 8; ++q) { h[q] = hist[lane * 8 + q]; t8 += h[q]; }
                int psum = t8;
                #pragma unroll
                for (int o = 1; o < 32; o <<= 1) {
                    int w = __shfl_down_sync(0xFFFFFFFFu, psum, o);
                    if (lane + o < 32) psum += w;
                }
                int above = psum - t8;
                if (above < remk && remk <= above + t8) {
                    int r = remk;
                    int c = above;
                    #pragma unroll
                    for (int q = 7; q >= 0; --q) {
                        if (r <= c + h[q]) {
                            s_pref = prefix | ((unsigned long long)(lane * 8 + q) << shift);
                            s_remk = r - c;
                            s_done = (r - c == h[q]) ? 1 : 0;
                            break;
                        }
                        c += h[q];
                    }
                }
            }
            __syncthreads();
            prefix = s_pref;
            remk = s_remk;
            if (s_done) break;
            __syncthreads();
        }
    }
    // exactly k keys satisfy key >= prefix

    // contiguous-chunk stable compaction (2 block barriers total)
    __shared__ int s_wincl[32];
    const int ce = (n + 1023) >> 10;        // elements per thread, contiguous
    const int start = tid * ce;
    int cnt = 0;
    for (int e = 0; e < ce; ++e) {
        int i = start + e;
        if (i < n && keys[i] >= prefix) cnt++;
    }
    int incl = cnt;
    #pragma unroll
    for (int o = 1; o < 32; o <<= 1) {
        int w = __shfl_up_sync(0xFFFFFFFFu, incl, o);
        if (lane >= o) incl += w;
    }
    if (lane == 31) s_wincl[wid] = incl;
    __syncthreads();
    if (wid == 0) {
        int v = s_wincl[lane];
        int sc = v;
        #pragma unroll
        for (int o = 1; o < 32; o <<= 1) {
            int w = __shfl_up_sync(0xFFFFFFFFu, sc, o);
            if (lane >= o) sc += w;
        }
        s_wincl[lane] = sc - v;   // exclusive over warps
    }
    __syncthreads();
    int pos = s_wincl[wid] + (incl - cnt);   // global stable rank base
    for (int e = 0; e < ce; ++e) {
        int i = start + e;
        if (i >= n) break;
        unsigned long long kk = keys[i];
        if (kk >= prefix) {
            int slot = c_cbase[lvl] + pos;
            pos++;
            int gidx = loff + i;
            unsigned int u = (unsigned int)(kk >> 32);
            unsigned int fb = (u & 0x80000000u) ? (u ^ 0x80000000u) : ~u;
            float score = __uint_as_float(fb);
            const float4 rg = ((const float4*)reg)[(size_t)b * NPTS + gidx];
            float2 p = ((const float2*)points)[gidx];
            float l = rg.x * IMGF, t = rg.y * IMGF;
            float r = rg.z * IMGF, bt = rg.w * IMGF;
            float x1 = fminf(fmaxf(p.x - l, 0.0f), IMGF);
            float y1 = fminf(fmaxf(p.y - t, 0.0f), IMGF);
            float x2 = fminf(fmaxf(p.x + r, 0.0f), IMGF);
            float y2 = fminf(fmaxf(p.y + bt, 0.0f), IMGF);
            int ci = b * NCAND + slot;
            g_cscore[ci] = score;
            g_cbox[ci] = make_float4(x1, y1, x2, y2);
            g_ckey[ci] = (score > 0.05f)
                       ? (((unsigned long long)u << 32) |
                          (unsigned long long)(0xFFFFFFFFu - (unsigned)slot))
                       : 0ULL;
        }
    }
}

// ---------------------------------------------------------------------------
// Stage 3a: per-image bitonic sort (desc) of candidate keys + gather.
// j<32 exchanges stay inside one warp's 32-element group -> warp sync only.
// ---------------------------------------------------------------------------
__global__ void __launch_bounds__(1024)
sort_kernel(int b0) {
    const int b = b0 + blockIdx.x;
    const int tid = threadIdx.x;
    __shared__ unsigned long long sk[4096];
    for (int i = tid; i < 4096; i += 1024)
        sk[i] = (i < NCAND) ? g_ckey[b * NCAND + i] : 0ULL;
    __syncthreads();

    for (int k = 2; k <= 4096; k <<= 1) {
        for (int j = k >> 1; j > 0; j >>= 1) {
            for (int i = tid; i < 4096; i += 1024) {
                int ixj = i ^ j;
                if (ixj > i) {
                    bool up = ((i & k) == 0);
                    unsigned long long a = sk[i], c = sk[ixj];
                    if ((a > c) == up) { sk[i] = c; sk[ixj] = a; }
                }
            }
            int jnext = (j > 1) ? (j >> 1) : k;   // next k's first stage j == k
            if (j >= 32 || jnext >= 32) __syncthreads();
            else                        __syncwarp();
        }
    }

    __shared__ int s_nv;
    if (tid == 0) s_nv = 0;
    __syncthreads();
    int cnt = 0;
    for (int p = tid; p < NCAND; p += 1024) {
        unsigned long long key = sk[4095 - p];
        if (key) {
            cnt++;
            int slot = (int)(0xFFFFFFFFu - (unsigned)key);
            float4 bx = g_cbox[b * NCAND + slot];
            g_sbox[b * NCAND + p] = bx;
            g_sscore[b * NCAND + p] = g_cscore[b * NCAND + slot];
            g_sarea[b * NCAND + p] = (bx.z - bx.x) * (bx.w - bx.y);
        } else {
            g_sbox[b * NCAND + p] = make_float4(0.f, 0.f, 0.f, 0.f);
            g_sscore[b * NCAND + p] = 0.f;
            g_sarea[b * NCAND + p] = 0.f;
        }
    }
    cnt += __shfl_down_sync(0xFFFFFFFFu, cnt, 16);
    cnt += __shfl_down_sync(0xFFFFFFFFu, cnt, 8);
    cnt += __shfl_down_sync(0xFFFFFFFFu, cnt, 4);
    cnt += __shfl_down_sync(0xFFFFFFFFu, cnt, 2);
    cnt += __shfl_down_sync(0xFFFFFFFFu, cnt, 1);
    if ((tid & 31) == 0) atomicAdd(&s_nv, cnt);
    __syncthreads();
    if (tid == 0) g_nvalid[b] = s_nv;
}

// ---------------------------------------------------------------------------
// exact "fl(inter/denom) > 0.5" without division on the common path:
//   inter <= 0.5*denom            -> quotient <= 0.5          -> false
//   inter >  denom*0.5000002      -> quotient >  0.5 + 2^-25  -> true
//   else (~4e-7 relative band)    -> exact IEEE division
// ---------------------------------------------------------------------------
__device__ __forceinline__ bool iou_gt_half(float inter, float denom) {
    bool sup = inter > 0.5f * denom;
    if (sup && inter <= __fmul_rn(denom, 0.5000002f))
        sup = (inter / denom > 0.5f);
    return sup;
}

// ---------------------------------------------------------------------------
// Stage 3b: suppression bit matrix, one warp per PAIR of rows
// (measured-best occupancy/ILP point); word loop bounded by nvalid.
// ---------------------------------------------------------------------------
__global__ void __launch_bounds__(256)
mask_kernel(int b0) {
    const int b = b0 + blockIdx.y;
    const int lane = threadIdx.x & 31;
    const int i0 = (blockIdx.x * 8 + (threadIdx.x >> 5)) * 2;
    const int nv = g_nvalid[b];
    if (i0 >= nv) return;
    const bool two = (i0 + 1 < nv);

    const float4 bA = g_sbox[b * NCAND + i0];
    const float  aA = g_sarea[b * NCAND + i0];
    const float4 bB = two ? g_sbox[b * NCAND + i0 + 1] : bA;
    const float  aB = two ? g_sarea[b * NCAND + i0 + 1] : aA;
    unsigned* rowA = g_mask + ((size_t)(b * NCAND) + i0) * NWORDS;
    unsigned* rowB = rowA + NWORDS;

    const int iw = i0 >> 5;
    const int jwmax = (nv + 31) >> 5;        // scan never reads words >= jwmax
    for (int jw = iw; jw < jwmax; ++jw) {
        const int j = jw * 32 + lane;
        float4 bj = make_float4(0.f, 0.f, 0.f, 0.f);
        float aj = 0.f;
        if (j < NCAND) {
            bj = g_sbox[b * NCAND + j];
            aj = g_sarea[b * NCAND + j];
        }
        bool supA = false;
        {
            float x1 = fmaxf(bA.x, bj.x), y1 = fmaxf(bA.y, bj.y);
            float x2 = fminf(bA.z, bj.z), y2 = fminf(bA.w, bj.w);
            float inter = fmaxf(x2 - x1, 0.0f) * fmaxf(y2 - y1, 0.0f);
            float denom = ((aA + aj) - inter) + 1e-9f;
            supA = (j > i0) && (j < NCAND) && iou_gt_half(inter, denom);
        }
        unsigned wA = __ballot_sync(0xFFFFFFFFu, supA);
        if (lane == 0) rowA[jw] = wA;
        bool supB = false;
        {
            float x1 = fmaxf(bB.x, bj.x), y1 = fmaxf(bB.y, bj.y);
            float x2 = fminf(bB.z, bj.z), y2 = fminf(bB.w, bj.w);
            float inter = fmaxf(x2 - x1, 0.0f) * fmaxf(y2 - y1, 0.0f);
            float denom = ((aB + aj) - inter) + 1e-9f;
            supB = (j > i0 + 1) && (j < NCAND) && iou_gt_half(inter, denom);
        }
        unsigned wB = __ballot_sync(0xFFFFFFFFu, supB);
        if (two && lane == 0) rowB[jw] = wB;
    }
}

// ---------------------------------------------------------------------------
// Stage 3c: serial greedy scan with bitmap suppression (one warp per image).
// Targeted prefetch: lanes 0-7 find first live bit in words w..w+7 of the
// current alive bitmap and prefetch those exact rows before the OR.
// ---------------------------------------------------------------------------
__global__ void __launch_bounds__(32)
scan_kernel(float* __restrict__ out, int b0) {
    const int b = b0 + blockIdx.x;
    const int lane = threadIdx.x;
    __shared__ uint4 S4[NCHUNK];
    if (lane < NCHUNK) S4[lane] = make_uint4(0u, 0u, 0u, 0u);
    __syncwarp();
    unsigned* S = (unsigned*)S4;

    const int nvalid = g_nvalid[b];
    const unsigned* mbase = g_mask + (size_t)b * NCAND * NWORDS;
    const int nw = (nvalid + 31) >> 5;
    const int nchunk = (nw + 3) >> 2;        // live chunk count
    const unsigned tailmask = (nvalid & 31) ? ((1u << (nvalid & 31)) - 1u)
                                            : 0xFFFFFFFFu;
    int picks = 0;

    for (int w = 0; w < nw && picks < MAXDET; ++w) {
        const unsigned lastmask = (w == nw - 1) ? tailmask : 0xFFFFFFFFu;
        const int cw = w >> 2;
        unsigned bits = ~S[w] & lastmask;
        while (bits && picks < MAXDET) {
            int bit = __ffs(bits) - 1;
            int i = w * 32 + bit;
            const unsigned above = ~((2u << bit) - 1u);

            // targeted prefetch: first live bit of words w..w+7 (pre-OR view)
            {
                int wl = w + lane;
                if (lane < 8 && wl < nw) {
                    unsigned bl;
                    if (lane == 0) bl = bits & above;
                    else {
                        bl = ~S[wl];
                        if (wl == nw - 1) bl &= tailmask;
                    }
                    if (bl) {
                        int pr = wl * 32 + (__ffs(bl) - 1);
                        const char* pp = (const char*)(mbase +
                            (size_t)pr * NWORDS + cw * 4);
                        asm volatile("prefetch.global.L1 [%0];" :: "l"(pp));
                        asm volatile("prefetch.global.L1 [%0];" :: "l"(pp + 128));
                        asm volatile("prefetch.global.L1 [%0];" :: "l"(pp + 256));
                        asm volatile("prefetch.global.L1 [%0];" :: "l"(pp + 384));
                    }
                }
            }

            // load row i chunks (issued before output writes)
            const bool doOR = (lane >= cw && lane < nchunk);
            uint4 r = make_uint4(0u, 0u, 0u, 0u);
            if (doOR)
                r = *((const uint4*)(mbase + (size_t)i * NWORDS) + lane);

            if (lane == 0) {
                int oslot = b * MAXDET + picks;
                float4 bx = g_sbox[b * NCAND + i];
                out[OFF_BOXES + (size_t)oslot * 4 + 0] = bx.x;
                out[OFF_BOXES + (size_t)oslot * 4 + 1] = bx.y;
                out[OFF_BOXES + (size_t)oslot * 4 + 2] = bx.z;
                out[OFF_BOXES + (size_t)oslot * 4 + 3] = bx.w;
                out[OFF_SCORES + oslot] = g_sscore[b * NCAND + i];
                out[OFF_LABELS + oslot] = 0.0f;
                out[OFF_VALID + oslot] = 1.0f;
            }
            picks++;

            if (doOR) {
                uint4 s = S4[lane];
                S4[lane] = make_uint4(s.x | r.x, s.y | r.y, s.z | r.z, s.w | r.w);
            }
            __syncwarp();
            bits = ~S[w] & lastmask & above;
        }
    }

    for (int jt = picks + lane; jt < MAXDET; jt += 32) {
        int oslot = b * MAXDET + jt;
        out[OFF_BOXES + (size_t)oslot * 4 + 0] = 0.0f;
        out[OFF_BOXES + (size_t)oslot * 4 + 1] = 0.0f;
        out[OFF_BOXES + (size_t)oslot * 4 + 2] = 0.0f;
        out[OFF_BOXES + (size_t)oslot * 4 + 3] = 0.0f;
        out[OFF_SCORES + oslot] = 0.0f;
        out[OFF_LABELS + oslot] = -1.0f;
        out[OFF_VALID + oslot] = 0.0f;
    }
}

extern "C" void kernel_launch(void* const* d_in, const int* in_sizes, int n_in,
                              void* d_out, int out_size) {
    const float* points = (const float*)d_in[0];   // (34100, 2)
    const float* gt     = (const float*)d_in[1];   // (8, 200, 4)
    const float* cls    = (const float*)d_in[2];   // (8, 34100, 1)
    const float* reg    = (const float*)d_in[3];   // (8, 34100, 4)
    float* out = (float*)d_out;

    // ONE extra stream (proven 0-byte overhead in R5-R7); two half-batch
    // pipelines: images 0-3 on the capture stream, images 4-7 on s2.
    static cudaStream_t s2 = nullptr;
    static cudaEvent_t e_fork = nullptr, e_join = nullptr;
    if (s2 == nullptr) {
        cudaStreamCreateWithFlags(&s2, cudaStreamNonBlocking);
        cudaEventCreateWithFlags(&e_fork, cudaEventDisableTiming);
        cudaEventCreateWithFlags(&e_join, cudaEventDisableTiming);
    }

    cudaEventRecord(e_fork, 0);
    cudaStreamWaitEvent(s2, e_fork, 0);

    const int maskblocks = (NCAND / 2 + 7) / 8;
    dim3 tg(NLVL, HALF);
    dim3 mk(maskblocks, HALF);
    dim3 mg((NPTS + 1023) / 1024, HALF);

    // pipeline A (capture stream): images 0-3
    topk_kernel<<<tg, 1024>>>(cls, reg, points, 0);
    sort_kernel<<<HALF, 1024>>>(0);
    mask_kernel<<<mk, 256>>>(0);
    scan_kernel<<<HALF, 32>>>(out, 0);
    match_kernel<<<mg, 256>>>(points, gt, out, 0);

    // pipeline B (s2): images 4-7
    topk_kernel<<<tg, 1024, 0, s2>>>(cls, reg, points, HALF);
    sort_kernel<<<HALF, 1024, 0, s2>>>(HALF);
    mask_kernel<<<mk, 256, 0, s2>>>(HALF);
    scan_kernel<<<HALF, 32, 0, s2>>>(out, HALF);
    match_kernel<<<mg, 256, 0, s2>>>(points, gt, out, HALF);
    cudaEventRecord(e_join, s2);

    cudaStreamWaitEvent(0, e_join, 0);
}